// round 1
// baseline (speedup 1.0000x reference)
#include <cuda_runtime.h>
#include <math.h>

#define D_MODEL 1024
#define N_HEADS 16
#define D_HEAD 64
#define FF_DIM 4096
#define SEQ 2048
#define BATCH 2
#define NTOK (BATCH * SEQ)  // 4096

// ---------------- scratch (static device arrays; no allocations) ----------------
__device__ float g_h[NTOK * D_MODEL];     // LN output (reused for both LNs)
__device__ float g_q[NTOK * D_MODEL];
__device__ float g_k[NTOK * D_MODEL];
__device__ float g_v[NTOK * D_MODEL];
__device__ float g_ctx[NTOK * D_MODEL];
__device__ float g_x1[NTOK * D_MODEL];    // after residual 1
__device__ float g_ff[NTOK * FF_DIM];     // FF hidden

// ---------------- LayerNorm: one block per row ----------------
__global__ void ln_kernel(const float* __restrict__ x, const float* __restrict__ gam,
                          const float* __restrict__ bet, float* __restrict__ y) {
    int row = blockIdx.x;
    const float* xr = x + (size_t)row * D_MODEL;
    float* yr = y + (size_t)row * D_MODEL;
    int tid = threadIdx.x;  // 256 threads, 4 elems each
    float4 v = *(const float4*)(xr + tid * 4);
    float s  = v.x + v.y + v.z + v.w;
    float ss = v.x * v.x + v.y * v.y + v.z * v.z + v.w * v.w;
    #pragma unroll
    for (int o = 16; o > 0; o >>= 1) {
        s  += __shfl_xor_sync(0xffffffffu, s, o);
        ss += __shfl_xor_sync(0xffffffffu, ss, o);
    }
    __shared__ float sh[16];
    int wid = tid >> 5, lane = tid & 31;
    if (lane == 0) { sh[wid] = s; sh[8 + wid] = ss; }
    __syncthreads();
    if (tid == 0) {
        float a = 0.f, b = 0.f;
        #pragma unroll
        for (int w = 0; w < 8; ++w) { a += sh[w]; b += sh[8 + w]; }
        sh[0] = a; sh[8] = b;
    }
    __syncthreads();
    float mu  = sh[0] * (1.0f / D_MODEL);
    float var = sh[8] * (1.0f / D_MODEL) - mu * mu;
    float r = rsqrtf(var + 1e-5f);
    float4 gv = *(const float4*)(gam + tid * 4);
    float4 bv = *(const float4*)(bet + tid * 4);
    float4 o;
    o.x = (v.x - mu) * r * gv.x + bv.x;
    o.y = (v.y - mu) * r * gv.y + bv.y;
    o.z = (v.z - mu) * r * gv.z + bv.z;
    o.w = (v.w - mu) * r * gv.w + bv.w;
    *(float4*)(yr + tid * 4) = o;
}

// ---------------- SGEMM: C = A[MxK] @ B[KxN] + bias (+R) (relu?) ----------------
#define BM 128
#define BN 128
#define BKS 8

template <bool RELU, bool RES>
__global__ void __launch_bounds__(256) sgemm_kernel(
    const float* __restrict__ A, const float* __restrict__ B,
    const float* __restrict__ bias, const float* __restrict__ R,
    float* __restrict__ C, int M, int N, int K) {
    __shared__ float As[BKS][BM];
    __shared__ float Bs[BKS][BN];
    int tid = threadIdx.x;
    int bm = blockIdx.y * BM;
    int bn = blockIdx.x * BN;
    int aRow = tid >> 1;          // 0..127
    int aCol = (tid & 1) << 2;    // 0 or 4
    int bRow = tid >> 5;          // 0..7
    int bCol = (tid & 31) << 2;   // 0..124
    int ty = tid >> 4, tx = tid & 15;
    float acc[8][8];
    #pragma unroll
    for (int i = 0; i < 8; ++i)
        #pragma unroll
        for (int j = 0; j < 8; ++j) acc[i][j] = 0.f;

    const float* Ap = A + (size_t)(bm + aRow) * K + aCol;
    const float* Bp = B + (size_t)bRow * N + bn + bCol;

    for (int kt = 0; kt < K; kt += BKS) {
        float4 a = *(const float4*)(Ap + kt);
        float4 b = *(const float4*)(Bp + (size_t)kt * N);
        As[aCol + 0][aRow] = a.x;
        As[aCol + 1][aRow] = a.y;
        As[aCol + 2][aRow] = a.z;
        As[aCol + 3][aRow] = a.w;
        *(float4*)&Bs[bRow][bCol] = b;
        __syncthreads();
        #pragma unroll
        for (int k = 0; k < BKS; ++k) {
            float ar[8], br[8];
            *(float4*)(ar)     = *(const float4*)&As[k][ty * 8];
            *(float4*)(ar + 4) = *(const float4*)&As[k][ty * 8 + 4];
            *(float4*)(br)     = *(const float4*)&Bs[k][tx * 8];
            *(float4*)(br + 4) = *(const float4*)&Bs[k][tx * 8 + 4];
            #pragma unroll
            for (int i = 0; i < 8; ++i)
                #pragma unroll
                for (int j = 0; j < 8; ++j)
                    acc[i][j] = fmaf(ar[i], br[j], acc[i][j]);
        }
        __syncthreads();
    }

    #pragma unroll
    for (int i = 0; i < 8; ++i) {
        size_t m = (size_t)(bm + ty * 8 + i);
        #pragma unroll
        for (int j = 0; j < 8; j += 4) {
            size_t n = (size_t)(bn + tx * 8 + j);
            float4 bs = *(const float4*)(bias + n);
            float4 c;
            c.x = acc[i][j + 0] + bs.x;
            c.y = acc[i][j + 1] + bs.y;
            c.z = acc[i][j + 2] + bs.z;
            c.w = acc[i][j + 3] + bs.w;
            if (RES) {
                float4 rr = *(const float4*)(R + m * N + n);
                c.x += rr.x; c.y += rr.y; c.z += rr.z; c.w += rr.w;
            }
            if (RELU) {
                c.x = fmaxf(c.x, 0.f); c.y = fmaxf(c.y, 0.f);
                c.z = fmaxf(c.z, 0.f); c.w = fmaxf(c.w, 0.f);
            }
            *(float4*)(C + m * N + n) = c;
        }
    }
}

// ---------------- Flash attention (fp32, online softmax) ----------------
// Tile: 64 queries x 64 keys, d_head = 64. 128 threads: ty=tid/8 (4 rows each),
// tx=tid%8 (8 cols each, strided by 8 -> conflict-free with PAD=65).
#define AQ 64
#define AKV 64
#define APAD 65
#define ATTN_SMEM_FLOATS (4 * AQ * APAD + AKV)

__global__ void __launch_bounds__(128) attn_kernel(
    const float* __restrict__ Q, const float* __restrict__ Kg,
    const float* __restrict__ Vg, const int* __restrict__ mask,
    float* __restrict__ O) {
    extern __shared__ float sm[];
    float (*Qs)[APAD] = (float(*)[APAD])(sm);
    float (*Ks)[APAD] = (float(*)[APAD])(sm + AQ * APAD);
    float (*Vs)[APAD] = (float(*)[APAD])(sm + 2 * AQ * APAD);
    float (*Ps)[APAD] = (float(*)[APAD])(sm + 3 * AQ * APAD);
    float* Ms = sm + 4 * AQ * APAD;

    int tid = threadIdx.x;
    int q0 = blockIdx.x * AQ;
    int b = blockIdx.y >> 4;
    int h = blockIdx.y & 15;
    const float scale = 0.125f;  // 1/sqrt(64)

    const float* Qb = Q  + ((size_t)(b * SEQ + q0)) * D_MODEL + h * D_HEAD;
    const float* Kb = Kg + ((size_t)(b * SEQ)) * D_MODEL + h * D_HEAD;
    const float* Vb = Vg + ((size_t)(b * SEQ)) * D_MODEL + h * D_HEAD;

    // load Q tile (pre-scaled)
    for (int idx = tid; idx < AQ * 16; idx += 128) {
        int r = idx >> 4, c4 = (idx & 15) << 2;
        float4 v = *(const float4*)(Qb + (size_t)r * D_MODEL + c4);
        Qs[r][c4 + 0] = v.x * scale;
        Qs[r][c4 + 1] = v.y * scale;
        Qs[r][c4 + 2] = v.z * scale;
        Qs[r][c4 + 3] = v.w * scale;
    }

    int ty = tid >> 3, tx = tid & 7;
    int r0 = ty * 4;
    float m_i[4] = {-1e30f, -1e30f, -1e30f, -1e30f};
    float l_i[4] = {0.f, 0.f, 0.f, 0.f};
    float acc[4][8];
    #pragma unroll
    for (int i = 0; i < 4; ++i)
        #pragma unroll
        for (int j = 0; j < 8; ++j) acc[i][j] = 0.f;

    for (int kt = 0; kt < SEQ; kt += AKV) {
        __syncthreads();  // previous PV done before K/V overwrite
        for (int idx = tid; idx < AKV * 16; idx += 128) {
            int r = idx >> 4, c4 = (idx & 15) << 2;
            float4 kv = *(const float4*)(Kb + (size_t)(kt + r) * D_MODEL + c4);
            Ks[r][c4 + 0] = kv.x; Ks[r][c4 + 1] = kv.y;
            Ks[r][c4 + 2] = kv.z; Ks[r][c4 + 3] = kv.w;
            float4 vv = *(const float4*)(Vb + (size_t)(kt + r) * D_MODEL + c4);
            Vs[r][c4 + 0] = vv.x; Vs[r][c4 + 1] = vv.y;
            Vs[r][c4 + 2] = vv.z; Vs[r][c4 + 3] = vv.w;
        }
        if (tid < AKV) Ms[tid] = (mask[b * SEQ + kt + tid] == 0) ? -1e30f : 0.0f;
        __syncthreads();

        // scores: S[r][c] = sum_d Qs[r][d] * Ks[c][d]   (cols: tx + 8*j)
        float s[4][8];
        #pragma unroll
        for (int i = 0; i < 4; ++i)
            #pragma unroll
            for (int j = 0; j < 8; ++j) s[i][j] = 0.f;
        #pragma unroll 8
        for (int d = 0; d < D_HEAD; ++d) {
            float kr[8];
            #pragma unroll
            for (int j = 0; j < 8; ++j) kr[j] = Ks[tx + 8 * j][d];
            #pragma unroll
            for (int i = 0; i < 4; ++i) {
                float qv = Qs[r0 + i][d];
                #pragma unroll
                for (int j = 0; j < 8; ++j) s[i][j] = fmaf(qv, kr[j], s[i][j]);
            }
        }
        // mask (additive -1e30 where mask==0)
        #pragma unroll
        for (int j = 0; j < 8; ++j) {
            float mv = Ms[tx + 8 * j];
            #pragma unroll
            for (int i = 0; i < 4; ++i) s[i][j] += mv;
        }
        // online softmax per row (row shared by 8 lanes: tx group -> shfl_xor 1,2,4)
        #pragma unroll
        for (int i = 0; i < 4; ++i) {
            float mloc = s[i][0];
            #pragma unroll
            for (int j = 1; j < 8; ++j) mloc = fmaxf(mloc, s[i][j]);
            #pragma unroll
            for (int o = 1; o < 8; o <<= 1)
                mloc = fmaxf(mloc, __shfl_xor_sync(0xffffffffu, mloc, o));
            float mnew = fmaxf(m_i[i], mloc);
            float alpha = __expf(m_i[i] - mnew);
            float lsum = 0.f;
            #pragma unroll
            for (int j = 0; j < 8; ++j) {
                float p = __expf(s[i][j] - mnew);
                s[i][j] = p;
                lsum += p;
            }
            #pragma unroll
            for (int o = 1; o < 8; o <<= 1)
                lsum += __shfl_xor_sync(0xffffffffu, lsum, o);
            l_i[i] = l_i[i] * alpha + lsum;
            m_i[i] = mnew;
            #pragma unroll
            for (int j = 0; j < 8; ++j) acc[i][j] *= alpha;
            #pragma unroll
            for (int j = 0; j < 8; ++j) Ps[r0 + i][tx + 8 * j] = s[i][j];
        }
        __syncthreads();

        // O += P @ V   (cols: tx + 8*jj)
        #pragma unroll 4
        for (int j = 0; j < AKV; ++j) {
            float vr[8];
            #pragma unroll
            for (int jj = 0; jj < 8; ++jj) vr[jj] = Vs[j][tx + 8 * jj];
            #pragma unroll
            for (int i = 0; i < 4; ++i) {
                float p = Ps[r0 + i][j];
                #pragma unroll
                for (int jj = 0; jj < 8; ++jj)
                    acc[i][jj] = fmaf(p, vr[jj], acc[i][jj]);
            }
        }
    }

    float* Ob = O + ((size_t)(b * SEQ + q0)) * D_MODEL + h * D_HEAD;
    #pragma unroll
    for (int i = 0; i < 4; ++i) {
        float inv = 1.0f / l_i[i];
        #pragma unroll
        for (int jj = 0; jj < 8; ++jj)
            Ob[(size_t)(r0 + i) * D_MODEL + tx + 8 * jj] = acc[i][jj] * inv;
    }
}

// ---------------- launch ----------------
extern "C" void kernel_launch(void* const* d_in, const int* in_sizes, int n_in,
                              void* d_out, int out_size) {
    const float* x     = (const float*)d_in[0];
    const int*   mask  = (const int*)d_in[1];
    const float* wq    = (const float*)d_in[2];
    const float* bq    = (const float*)d_in[3];
    const float* wk    = (const float*)d_in[4];
    const float* bk    = (const float*)d_in[5];
    const float* wv    = (const float*)d_in[6];
    const float* bv    = (const float*)d_in[7];
    const float* wo    = (const float*)d_in[8];
    const float* bo    = (const float*)d_in[9];
    const float* ln1_g = (const float*)d_in[10];
    const float* ln1_b = (const float*)d_in[11];
    const float* ln2_g = (const float*)d_in[12];
    const float* ln2_b = (const float*)d_in[13];
    const float* w1    = (const float*)d_in[14];
    const float* b1    = (const float*)d_in[15];
    const float* w2    = (const float*)d_in[16];
    const float* b2    = (const float*)d_in[17];
    float* out = (float*)d_out;

    float *h, *q, *k, *v, *ctx, *x1, *ff;
    cudaGetSymbolAddress((void**)&h,   g_h);
    cudaGetSymbolAddress((void**)&q,   g_q);
    cudaGetSymbolAddress((void**)&k,   g_k);
    cudaGetSymbolAddress((void**)&v,   g_v);
    cudaGetSymbolAddress((void**)&ctx, g_ctx);
    cudaGetSymbolAddress((void**)&x1,  g_x1);
    cudaGetSymbolAddress((void**)&ff,  g_ff);

    // LN1
    ln_kernel<<<NTOK, 256>>>(x, ln1_g, ln1_b, h);

    // Q/K/V projections
    dim3 g1(D_MODEL / BN, NTOK / BM);
    sgemm_kernel<false, false><<<g1, 256>>>(h, wq, bq, nullptr, q, NTOK, D_MODEL, D_MODEL);
    sgemm_kernel<false, false><<<g1, 256>>>(h, wk, bk, nullptr, k, NTOK, D_MODEL, D_MODEL);
    sgemm_kernel<false, false><<<g1, 256>>>(h, wv, bv, nullptr, v, NTOK, D_MODEL, D_MODEL);

    // attention
    static const int attn_smem = ATTN_SMEM_FLOATS * (int)sizeof(float);
    cudaFuncSetAttribute(attn_kernel, cudaFuncAttributeMaxDynamicSharedMemorySize, attn_smem);
    dim3 ga(SEQ / AQ, BATCH * N_HEADS);
    attn_kernel<<<ga, 128, attn_smem>>>(q, k, v, mask, ctx);

    // O projection + residual 1
    sgemm_kernel<false, true><<<g1, 256>>>(ctx, wo, bo, x, x1, NTOK, D_MODEL, D_MODEL);

    // LN2
    ln_kernel<<<NTOK, 256>>>(x1, ln2_g, ln2_b, h);

    // FF1 + ReLU
    dim3 g2(FF_DIM / BN, NTOK / BM);
    sgemm_kernel<true, false><<<g2, 256>>>(h, w1, b1, nullptr, ff, NTOK, FF_DIM, D_MODEL);

    // FF2 + residual 2 -> out
    dim3 g3(D_MODEL / BN, NTOK / BM);
    sgemm_kernel<false, true><<<g3, 256>>>(ff, w2, b2, x1, out, NTOK, D_MODEL, FF_DIM);
}

// round 4
// speedup vs baseline: 1.5988x; 1.5988x over previous
#include <cuda_runtime.h>
#include <cuda_bf16.h>
#include <cstdint>
#include <math.h>

#define D_MODEL 1024
#define N_HEADS 16
#define D_HEAD 64
#define FF_DIM 4096
#define SEQ 2048
#define BATCH 2
#define NTOK (BATCH * SEQ)  // 4096

// ---------------- scratch (static device arrays; no allocations) ----------------
__device__ float g_h[NTOK * D_MODEL];
__device__ float g_q[NTOK * D_MODEL];
__device__ float g_k[NTOK * D_MODEL];
__device__ float g_v[NTOK * D_MODEL];
__device__ float g_ctx[NTOK * D_MODEL];
__device__ float g_x1[NTOK * D_MODEL];
__device__ float g_ff[NTOK * FF_DIM];
__device__ __nv_bfloat16 s_ah[NTOK * FF_DIM];
__device__ __nv_bfloat16 s_al[NTOK * FF_DIM];
__device__ __nv_bfloat16 s_wh[FF_DIM * D_MODEL];
__device__ __nv_bfloat16 s_wl[FF_DIM * D_MODEL];

// ======================= PTX helpers (sm_80-compatible) =======================
__device__ __forceinline__ uint32_t smem_u32(const void* p) {
    uint32_t a;
    asm("{ .reg .u64 t; cvta.to.shared.u64 t, %1; cvt.u32.u64 %0, t; }" : "=r"(a) : "l"(p));
    return a;
}
#define CP_ASYNC16(dst, src) \
    asm volatile("cp.async.cg.shared.global [%0], [%1], 16;" :: "r"(dst), "l"(src))
#define CP_COMMIT() asm volatile("cp.async.commit_group;" ::: "memory")
#define CP_WAIT1() asm volatile("cp.async.wait_group 1;" ::: "memory")
#define CP_WAIT0() asm volatile("cp.async.wait_group 0;" ::: "memory")

#define LDSM4(r0, r1, r2, r3, addr) \
    asm volatile("ldmatrix.sync.aligned.m8n8.x4.shared.b16 {%0,%1,%2,%3}, [%4];" \
                 : "=r"(r0), "=r"(r1), "=r"(r2), "=r"(r3) : "r"(addr))

__device__ __forceinline__ void mma16816(float* d, uint32_t a0, uint32_t a1,
                                         uint32_t a2, uint32_t a3,
                                         uint32_t b0, uint32_t b1) {
    asm volatile(
        "mma.sync.aligned.m16n8k16.row.col.f32.bf16.bf16.f32 "
        "{%0,%1,%2,%3}, {%4,%5,%6,%7}, {%8,%9}, {%0,%1,%2,%3};"
        : "+f"(d[0]), "+f"(d[1]), "+f"(d[2]), "+f"(d[3])
        : "r"(a0), "r"(a1), "r"(a2), "r"(a3), "r"(b0), "r"(b1));
}

__device__ __forceinline__ uint32_t sw128(uint32_t off) {
    return off ^ ((off >> 3) & 0x70);
}

// ======================= bf16x3 tensor-core GEMM ==============================
// C[M,N] = A[M,K] @ B^T + bias (+R)(relu). A,B bf16 hi/lo, [M,K]/[N,K] row-major.
// CTA tile 128x128, BK=64, 8 warps (2m x 4n), warp tile 64x32, m16n8k16 bf16.
#define GTILE 16384                       // one 128x64 bf16 tile in smem
#define GSMEM_TOTAL (4 * GTILE)           // A0 B0 A1 B1

template <bool RELU, bool RES>
__global__ void __launch_bounds__(256, 1) mma_gemm(
    const __nv_bfloat16* __restrict__ Ah, const __nv_bfloat16* __restrict__ Al,
    const __nv_bfloat16* __restrict__ Bh, const __nv_bfloat16* __restrict__ Bl,
    const float* __restrict__ bias, const float* __restrict__ R,
    float* __restrict__ C, int M, int N, int K) {
    extern __shared__ char smem[];
    const uint32_t sb = smem_u32(smem);
    const int tid = threadIdx.x;
    const int lane = tid & 31;
    const int w = tid >> 5;
    const int wm = w >> 2;        // 0..1
    const int wn = w & 3;         // 0..3
    const int bm = blockIdx.y * 128;
    const int bn = blockIdx.x * 128;

    const int kchunks = K >> 6;
    const int n_iter = 3 * kchunks;

    // fill row/chunk for cp.async (each thread: 4 A slots + 4 B slots)
    const int frow = tid >> 3;      // 0..31 (+32 each t)
    const int fch = tid & 7;        // 0..7

    auto issue = [&](int it, int buf) {
        int seg = it / kchunks;
        int kt = (it - seg * kchunks) << 6;
        const __nv_bfloat16* Aseg = (seg == 2) ? Al : Ah;
        const __nv_bfloat16* Bseg = (seg == 1) ? Bl : Bh;
        uint32_t dstA = sb + buf * 2 * GTILE;
        uint32_t dstB = dstA + GTILE;
        #pragma unroll
        for (int t = 0; t < 4; ++t) {
            int row = frow + t * 32;
            uint32_t so = sw128((uint32_t)(row * 128 + fch * 16));
            CP_ASYNC16(dstA + so, Aseg + (size_t)(bm + row) * K + kt + fch * 8);
            CP_ASYNC16(dstB + so, Bseg + (size_t)(bn + row) * K + kt + fch * 8);
        }
    };

    float acc[4][4][4];
    #pragma unroll
    for (int mt = 0; mt < 4; ++mt)
        #pragma unroll
        for (int nt = 0; nt < 4; ++nt)
            #pragma unroll
            for (int e = 0; e < 4; ++e) acc[mt][nt][e] = 0.f;

    issue(0, 0); CP_COMMIT();
    if (n_iter > 1) { issue(1, 1); CP_COMMIT(); }

    // per-lane ldmatrix row/col components (within tile)
    const int a_row_base = wm * 64 + (lane & 15);        // + mt*16
    const int a_cb = (lane >> 4) << 4;                   // 0 or 16 bytes
    const int b_row_base = wn * 32 + (lane & 7) + ((lane >> 4) << 3);  // + nt2*16
    const int b_cb = ((lane >> 3) & 1) << 4;

    for (int it = 0; it < n_iter; ++it) {
        int buf = it & 1;
        if (it + 2 < n_iter) { CP_WAIT1(); } else { CP_WAIT0(); }
        __syncthreads();

        uint32_t sA = sb + buf * 2 * GTILE;
        uint32_t sB = sA + GTILE;

        #pragma unroll
        for (int ks = 0; ks < 4; ++ks) {
            uint32_t a[4][4];
            #pragma unroll
            for (int mt = 0; mt < 4; ++mt) {
                uint32_t off = (uint32_t)((a_row_base + mt * 16) * 128 + ks * 32 + a_cb);
                LDSM4(a[mt][0], a[mt][1], a[mt][2], a[mt][3], sA + sw128(off));
            }
            uint32_t b[2][4];
            #pragma unroll
            for (int nt2 = 0; nt2 < 2; ++nt2) {
                uint32_t off = (uint32_t)((b_row_base + nt2 * 16) * 128 + ks * 32 + b_cb);
                LDSM4(b[nt2][0], b[nt2][1], b[nt2][2], b[nt2][3], sB + sw128(off));
            }
            #pragma unroll
            for (int mt = 0; mt < 4; ++mt)
                #pragma unroll
                for (int nt = 0; nt < 4; ++nt)
                    mma16816(acc[mt][nt], a[mt][0], a[mt][1], a[mt][2], a[mt][3],
                             b[nt >> 1][(nt & 1) * 2], b[nt >> 1][(nt & 1) * 2 + 1]);
        }
        __syncthreads();
        if (it + 2 < n_iter) { issue(it + 2, buf); CP_COMMIT(); }
    }

    // epilogue
    const int r0 = lane >> 2;
    const int c0 = (lane & 3) * 2;
    #pragma unroll
    for (int mt = 0; mt < 4; ++mt) {
        #pragma unroll
        for (int rr = 0; rr < 2; ++rr) {
            size_t m = (size_t)(bm + wm * 64 + mt * 16 + r0 + rr * 8);
            #pragma unroll
            for (int nt = 0; nt < 4; ++nt) {
                int n = bn + wn * 32 + nt * 8 + c0;
                float2 bv = *(const float2*)(bias + n);
                float vx = acc[mt][nt][rr * 2 + 0] + bv.x;
                float vy = acc[mt][nt][rr * 2 + 1] + bv.y;
                if (RES) {
                    float2 rv = *(const float2*)(R + m * N + n);
                    vx += rv.x; vy += rv.y;
                }
                if (RELU) { vx = fmaxf(vx, 0.f); vy = fmaxf(vy, 0.f); }
                *(float2*)(C + m * N + n) = make_float2(vx, vy);
            }
        }
    }
}

// ---------------- bf16 split (activations) ----------------
__global__ void split_kernel(const float* __restrict__ x, __nv_bfloat16* __restrict__ hi,
                             __nv_bfloat16* __restrict__ lo, int n) {
    int i = (blockIdx.x * 256 + threadIdx.x) * 4;
    if (i >= n) return;
    float4 v = *(const float4*)(x + i);
    float a[4] = { v.x, v.y, v.z, v.w };
    __nv_bfloat16 h[4], l[4];
    #pragma unroll
    for (int j = 0; j < 4; ++j) {
        h[j] = __float2bfloat16(a[j]);
        l[j] = __float2bfloat16(a[j] - __bfloat162float(h[j]));
    }
    __nv_bfloat162* ph = (__nv_bfloat162*)(hi + i);
    __nv_bfloat162* pl = (__nv_bfloat162*)(lo + i);
    ph[0] = __nv_bfloat162(h[0], h[1]); ph[1] = __nv_bfloat162(h[2], h[3]);
    pl[0] = __nv_bfloat162(l[0], l[1]); pl[1] = __nv_bfloat162(l[2], l[3]);
}

// ---------------- weight transpose + split: W[K,N] fp32 -> WT[N,K] bf16 hi/lo ----
__global__ void wsplit_kernel(const float* __restrict__ W, __nv_bfloat16* __restrict__ Th,
                              __nv_bfloat16* __restrict__ Tl, int K, int N) {
    __shared__ float t[32][33];
    int n0 = blockIdx.x * 32, k0 = blockIdx.y * 32;
    int tx = threadIdx.x, ty = threadIdx.y;
    #pragma unroll
    for (int i = ty; i < 32; i += 8)
        t[i][tx] = W[(size_t)(k0 + i) * N + n0 + tx];
    __syncthreads();
    #pragma unroll
    for (int i = ty; i < 32; i += 8) {
        float v = t[tx][i];
        __nv_bfloat16 h = __float2bfloat16(v);
        __nv_bfloat16 l = __float2bfloat16(v - __bfloat162float(h));
        size_t o = (size_t)(n0 + i) * K + k0 + tx;
        Th[o] = h;
        Tl[o] = l;
    }
}

// ---------------- LayerNorm: one block per row ----------------
__global__ void ln_kernel(const float* __restrict__ x, const float* __restrict__ gam,
                          const float* __restrict__ bet, float* __restrict__ y) {
    int row = blockIdx.x;
    const float* xr = x + (size_t)row * D_MODEL;
    float* yr = y + (size_t)row * D_MODEL;
    int tid = threadIdx.x;
    float4 v = *(const float4*)(xr + tid * 4);
    float s  = v.x + v.y + v.z + v.w;
    float ss = v.x * v.x + v.y * v.y + v.z * v.z + v.w * v.w;
    #pragma unroll
    for (int o = 16; o > 0; o >>= 1) {
        s  += __shfl_xor_sync(0xffffffffu, s, o);
        ss += __shfl_xor_sync(0xffffffffu, ss, o);
    }
    __shared__ float sh[16];
    int wid = tid >> 5, lane = tid & 31;
    if (lane == 0) { sh[wid] = s; sh[8 + wid] = ss; }
    __syncthreads();
    if (tid == 0) {
        float a = 0.f, b = 0.f;
        #pragma unroll
        for (int w = 0; w < 8; ++w) { a += sh[w]; b += sh[8 + w]; }
        sh[0] = a; sh[8] = b;
    }
    __syncthreads();
    float mu  = sh[0] * (1.0f / D_MODEL);
    float var = sh[8] * (1.0f / D_MODEL) - mu * mu;
    float r = rsqrtf(var + 1e-5f);
    float4 gv = *(const float4*)(gam + tid * 4);
    float4 bv = *(const float4*)(bet + tid * 4);
    float4 o;
    o.x = (v.x - mu) * r * gv.x + bv.x;
    o.y = (v.y - mu) * r * gv.y + bv.y;
    o.z = (v.z - mu) * r * gv.z + bv.z;
    o.w = (v.w - mu) * r * gv.w + bv.w;
    *(float4*)(yr + tid * 4) = o;
}

// ---------------- Flash attention (fp32, online softmax) ----------------
#define AQ 64
#define AKV 64
#define APAD 65
#define ATTN_SMEM_FLOATS (4 * AQ * APAD + AKV)

__global__ void __launch_bounds__(128) attn_kernel(
    const float* __restrict__ Q, const float* __restrict__ Kg,
    const float* __restrict__ Vg, const int* __restrict__ mask,
    float* __restrict__ O) {
    extern __shared__ float sm[];
    float (*Qs)[APAD] = (float(*)[APAD])(sm);
    float (*Ks)[APAD] = (float(*)[APAD])(sm + AQ * APAD);
    float (*Vs)[APAD] = (float(*)[APAD])(sm + 2 * AQ * APAD);
    float (*Ps)[APAD] = (float(*)[APAD])(sm + 3 * AQ * APAD);
    float* Ms = sm + 4 * AQ * APAD;

    int tid = threadIdx.x;
    int q0 = blockIdx.x * AQ;
    int b = blockIdx.y >> 4;
    int h = blockIdx.y & 15;
    const float scale = 0.125f;

    const float* Qb = Q  + ((size_t)(b * SEQ + q0)) * D_MODEL + h * D_HEAD;
    const float* Kb = Kg + ((size_t)(b * SEQ)) * D_MODEL + h * D_HEAD;
    const float* Vb = Vg + ((size_t)(b * SEQ)) * D_MODEL + h * D_HEAD;

    for (int idx = tid; idx < AQ * 16; idx += 128) {
        int r = idx >> 4, c4 = (idx & 15) << 2;
        float4 v = *(const float4*)(Qb + (size_t)r * D_MODEL + c4);
        Qs[r][c4 + 0] = v.x * scale;
        Qs[r][c4 + 1] = v.y * scale;
        Qs[r][c4 + 2] = v.z * scale;
        Qs[r][c4 + 3] = v.w * scale;
    }

    int ty = tid >> 3, tx = tid & 7;
    int r0 = ty * 4;
    float m_i[4] = {-1e30f, -1e30f, -1e30f, -1e30f};
    float l_i[4] = {0.f, 0.f, 0.f, 0.f};
    float acc[4][8];
    #pragma unroll
    for (int i = 0; i < 4; ++i)
        #pragma unroll
        for (int j = 0; j < 8; ++j) acc[i][j] = 0.f;

    for (int kt = 0; kt < SEQ; kt += AKV) {
        __syncthreads();
        for (int idx = tid; idx < AKV * 16; idx += 128) {
            int r = idx >> 4, c4 = (idx & 15) << 2;
            float4 kv = *(const float4*)(Kb + (size_t)(kt + r) * D_MODEL + c4);
            Ks[r][c4 + 0] = kv.x; Ks[r][c4 + 1] = kv.y;
            Ks[r][c4 + 2] = kv.z; Ks[r][c4 + 3] = kv.w;
            float4 vv = *(const float4*)(Vb + (size_t)(kt + r) * D_MODEL + c4);
            Vs[r][c4 + 0] = vv.x; Vs[r][c4 + 1] = vv.y;
            Vs[r][c4 + 2] = vv.z; Vs[r][c4 + 3] = vv.w;
        }
        if (tid < AKV) Ms[tid] = (mask[b * SEQ + kt + tid] == 0) ? -1e30f : 0.0f;
        __syncthreads();

        float s[4][8];
        #pragma unroll
        for (int i = 0; i < 4; ++i)
            #pragma unroll
            for (int j = 0; j < 8; ++j) s[i][j] = 0.f;
        #pragma unroll 8
        for (int d = 0; d < D_HEAD; ++d) {
            float kr[8];
            #pragma unroll
            for (int j = 0; j < 8; ++j) kr[j] = Ks[tx + 8 * j][d];
            #pragma unroll
            for (int i = 0; i < 4; ++i) {
                float qv = Qs[r0 + i][d];
                #pragma unroll
                for (int j = 0; j < 8; ++j) s[i][j] = fmaf(qv, kr[j], s[i][j]);
            }
        }
        #pragma unroll
        for (int j = 0; j < 8; ++j) {
            float mv = Ms[tx + 8 * j];
            #pragma unroll
            for (int i = 0; i < 4; ++i) s[i][j] += mv;
        }
        #pragma unroll
        for (int i = 0; i < 4; ++i) {
            float mloc = s[i][0];
            #pragma unroll
            for (int j = 1; j < 8; ++j) mloc = fmaxf(mloc, s[i][j]);
            #pragma unroll
            for (int o = 1; o < 8; o <<= 1)
                mloc = fmaxf(mloc, __shfl_xor_sync(0xffffffffu, mloc, o));
            float mnew = fmaxf(m_i[i], mloc);
            float alpha = __expf(m_i[i] - mnew);
            float lsum = 0.f;
            #pragma unroll
            for (int j = 0; j < 8; ++j) {
                float p = __expf(s[i][j] - mnew);
                s[i][j] = p;
                lsum += p;
            }
            #pragma unroll
            for (int o = 1; o < 8; o <<= 1)
                lsum += __shfl_xor_sync(0xffffffffu, lsum, o);
            l_i[i] = l_i[i] * alpha + lsum;
            m_i[i] = mnew;
            #pragma unroll
            for (int j = 0; j < 8; ++j) acc[i][j] *= alpha;
            #pragma unroll
            for (int j = 0; j < 8; ++j) Ps[r0 + i][tx + 8 * j] = s[i][j];
        }
        __syncthreads();

        #pragma unroll 4
        for (int j = 0; j < AKV; ++j) {
            float vr[8];
            #pragma unroll
            for (int jj = 0; jj < 8; ++jj) vr[jj] = Vs[j][tx + 8 * jj];
            #pragma unroll
            for (int i = 0; i < 4; ++i) {
                float p = Ps[r0 + i][j];
                #pragma unroll
                for (int jj = 0; jj < 8; ++jj)
                    acc[i][jj] = fmaf(p, vr[jj], acc[i][jj]);
            }
        }
    }

    float* Ob = O + ((size_t)(b * SEQ + q0)) * D_MODEL + h * D_HEAD;
    #pragma unroll
    for (int i = 0; i < 4; ++i) {
        float inv = 1.0f / l_i[i];
        #pragma unroll
        for (int jj = 0; jj < 8; ++jj)
            Ob[(size_t)(r0 + i) * D_MODEL + tx + 8 * jj] = acc[i][jj] * inv;
    }
}

// ---------------- launch ----------------
extern "C" void kernel_launch(void* const* d_in, const int* in_sizes, int n_in,
                              void* d_out, int out_size) {
    const float* x     = (const float*)d_in[0];
    const int*   mask  = (const int*)d_in[1];
    const float* wq    = (const float*)d_in[2];
    const float* bq    = (const float*)d_in[3];
    const float* wk    = (const float*)d_in[4];
    const float* bk    = (const float*)d_in[5];
    const float* wv    = (const float*)d_in[6];
    const float* bv    = (const float*)d_in[7];
    const float* wo    = (const float*)d_in[8];
    const float* bo    = (const float*)d_in[9];
    const float* ln1_g = (const float*)d_in[10];
    const float* ln1_b = (const float*)d_in[11];
    const float* ln2_g = (const float*)d_in[12];
    const float* ln2_b = (const float*)d_in[13];
    const float* w1    = (const float*)d_in[14];
    const float* b1    = (const float*)d_in[15];
    const float* w2    = (const float*)d_in[16];
    const float* b2    = (const float*)d_in[17];
    float* out = (float*)d_out;

    float *h, *q, *k, *v, *ctx, *x1, *ff;
    __nv_bfloat16 *ah, *al, *wh, *wl;
    cudaGetSymbolAddress((void**)&h,   g_h);
    cudaGetSymbolAddress((void**)&q,   g_q);
    cudaGetSymbolAddress((void**)&k,   g_k);
    cudaGetSymbolAddress((void**)&v,   g_v);
    cudaGetSymbolAddress((void**)&ctx, g_ctx);
    cudaGetSymbolAddress((void**)&x1,  g_x1);
    cudaGetSymbolAddress((void**)&ff,  g_ff);
    cudaGetSymbolAddress((void**)&ah,  s_ah);
    cudaGetSymbolAddress((void**)&al,  s_al);
    cudaGetSymbolAddress((void**)&wh,  s_wh);
    cudaGetSymbolAddress((void**)&wl,  s_wl);

    cudaFuncSetAttribute(mma_gemm<false, false>, cudaFuncAttributeMaxDynamicSharedMemorySize, GSMEM_TOTAL);
    cudaFuncSetAttribute(mma_gemm<false, true>,  cudaFuncAttributeMaxDynamicSharedMemorySize, GSMEM_TOTAL);
    cudaFuncSetAttribute(mma_gemm<true, false>,  cudaFuncAttributeMaxDynamicSharedMemorySize, GSMEM_TOTAL);
    static const int attn_smem = ATTN_SMEM_FLOATS * (int)sizeof(float);
    cudaFuncSetAttribute(attn_kernel, cudaFuncAttributeMaxDynamicSharedMemorySize, attn_smem);

    dim3 wsb(32, 8);
    dim3 gD(D_MODEL / 128, NTOK / 128);   // (8, 32)
    dim3 gF(FF_DIM / 128, NTOK / 128);    // (32, 32)
    const int splitD = (NTOK * D_MODEL) / (256 * 4);
    const int splitF = (NTOK * FF_DIM) / (256 * 4);

    // --- residual 1: LN1 -> QKV -> attention -> O-proj + residual ---
    ln_kernel<<<NTOK, 256>>>(x, ln1_g, ln1_b, h);
    split_kernel<<<splitD, 256>>>(h, ah, al, NTOK * D_MODEL);

    wsplit_kernel<<<dim3(D_MODEL / 32, D_MODEL / 32), wsb>>>(wq, wh, wl, D_MODEL, D_MODEL);
    mma_gemm<false, false><<<gD, 256, GSMEM_TOTAL>>>(ah, al, wh, wl, bq, nullptr, q, NTOK, D_MODEL, D_MODEL);
    wsplit_kernel<<<dim3(D_MODEL / 32, D_MODEL / 32), wsb>>>(wk, wh, wl, D_MODEL, D_MODEL);
    mma_gemm<false, false><<<gD, 256, GSMEM_TOTAL>>>(ah, al, wh, wl, bk, nullptr, k, NTOK, D_MODEL, D_MODEL);
    wsplit_kernel<<<dim3(D_MODEL / 32, D_MODEL / 32), wsb>>>(wv, wh, wl, D_MODEL, D_MODEL);
    mma_gemm<false, false><<<gD, 256, GSMEM_TOTAL>>>(ah, al, wh, wl, bv, nullptr, v, NTOK, D_MODEL, D_MODEL);

    attn_kernel<<<dim3(SEQ / AQ, BATCH * N_HEADS), 128, attn_smem>>>(q, k, v, mask, ctx);

    split_kernel<<<splitD, 256>>>(ctx, ah, al, NTOK * D_MODEL);
    wsplit_kernel<<<dim3(D_MODEL / 32, D_MODEL / 32), wsb>>>(wo, wh, wl, D_MODEL, D_MODEL);
    mma_gemm<false, true><<<gD, 256, GSMEM_TOTAL>>>(ah, al, wh, wl, bo, x, x1, NTOK, D_MODEL, D_MODEL);

    // --- residual 2: LN2 -> FF1(relu) -> FF2 + residual ---
    ln_kernel<<<NTOK, 256>>>(x1, ln2_g, ln2_b, h);
    split_kernel<<<splitD, 256>>>(h, ah, al, NTOK * D_MODEL);
    wsplit_kernel<<<dim3(FF_DIM / 32, D_MODEL / 32), wsb>>>(w1, wh, wl, D_MODEL, FF_DIM);
    mma_gemm<true, false><<<gF, 256, GSMEM_TOTAL>>>(ah, al, wh, wl, b1, nullptr, ff, NTOK, FF_DIM, D_MODEL);

    split_kernel<<<splitF, 256>>>(ff, ah, al, NTOK * FF_DIM);
    wsplit_kernel<<<dim3(D_MODEL / 32, FF_DIM / 32), wsb>>>(w2, wh, wl, FF_DIM, D_MODEL);
    mma_gemm<false, true><<<gD, 256, GSMEM_TOTAL>>>(ah, al, wh, wl, b2, x1, out, NTOK, D_MODEL, FF_DIM);
}

// round 5
// speedup vs baseline: 1.8921x; 1.1834x over previous
#include <cuda_runtime.h>
#include <cuda_bf16.h>
#include <cstdint>
#include <math.h>

#define D_MODEL 1024
#define N_HEADS 16
#define D_HEAD 64
#define FF_DIM 4096
#define SEQ 2048
#define BATCH 2
#define NTOK (BATCH * SEQ)  // 4096
#define QKV_N 3072

// ---------------- scratch (static device arrays; no allocations) ----------------
__device__ float g_qkv[NTOK * QKV_N];          // fused QKV output (fp32)
__device__ float g_x1[NTOK * D_MODEL];         // after residual 1
__device__ float g_bqkv[QKV_N];                // packed bias
__device__ __nv_bfloat16 s_ah[NTOK * D_MODEL]; // activation hi (LN out / ctx)
__device__ __nv_bfloat16 s_al[NTOK * D_MODEL];
__device__ __nv_bfloat16 s_fh[NTOK * FF_DIM];  // FF hidden hi
__device__ __nv_bfloat16 s_fl[NTOK * FF_DIM];
__device__ __nv_bfloat16 s_wh[FF_DIM * D_MODEL]; // weight hi (packed/transposed)
__device__ __nv_bfloat16 s_wl[FF_DIM * D_MODEL];

// ======================= PTX helpers (sm_80-compatible) =======================
__device__ __forceinline__ uint32_t smem_u32(const void* p) {
    uint32_t a;
    asm("{ .reg .u64 t; cvta.to.shared.u64 t, %1; cvt.u32.u64 %0, t; }" : "=r"(a) : "l"(p));
    return a;
}
#define CP_ASYNC16(dst, src) \
    asm volatile("cp.async.cg.shared.global [%0], [%1], 16;" :: "r"(dst), "l"(src))
#define CP_COMMIT() asm volatile("cp.async.commit_group;" ::: "memory")
#define CP_WAIT2() asm volatile("cp.async.wait_group 2;" ::: "memory")
#define CP_WAIT1() asm volatile("cp.async.wait_group 1;" ::: "memory")
#define CP_WAIT0() asm volatile("cp.async.wait_group 0;" ::: "memory")

#define LDSM4(r0, r1, r2, r3, addr) \
    asm volatile("ldmatrix.sync.aligned.m8n8.x4.shared.b16 {%0,%1,%2,%3}, [%4];" \
                 : "=r"(r0), "=r"(r1), "=r"(r2), "=r"(r3) : "r"(addr))

__device__ __forceinline__ void mma16816(float* d, const uint32_t* a,
                                         uint32_t b0, uint32_t b1) {
    asm volatile(
        "mma.sync.aligned.m16n8k16.row.col.f32.bf16.bf16.f32 "
        "{%0,%1,%2,%3}, {%4,%5,%6,%7}, {%8,%9}, {%0,%1,%2,%3};"
        : "+f"(d[0]), "+f"(d[1]), "+f"(d[2]), "+f"(d[3])
        : "r"(a[0]), "r"(a[1]), "r"(a[2]), "r"(a[3]), "r"(b0), "r"(b1));
}

__device__ __forceinline__ uint32_t sw128(uint32_t off) {
    return off ^ ((off >> 3) & 0x70);
}

// ======================= bf16x3 tensor-core GEMM (merged segments) ============
// C[M,N] = A@B^T + bias (+R)(relu). Per K-chunk(64) load Ah/Al/Bh/Bl tiles once,
// run 3 MMA sweeps (AhBh + AhBl + AlBh) into fp32 acc. CTA 128x128, 8 warps,
// 3-stage cp.async pipeline. SPLIT: emit bf16 hi/lo instead of fp32 C.
#define TILE_B 16384                      // one 128x64 bf16 tile
#define STAGE_B (4 * TILE_B)              // Ah Al Bh Bl = 64 KB
#define NSTAGES 3
#define GSMEM_TOTAL (NSTAGES * STAGE_B)   // 192 KB

template <bool RELU, bool RES, bool SPLIT>
__global__ void __launch_bounds__(256, 1) mma_gemm(
    const __nv_bfloat16* __restrict__ Ah, const __nv_bfloat16* __restrict__ Al,
    const __nv_bfloat16* __restrict__ Bh, const __nv_bfloat16* __restrict__ Bl,
    const float* __restrict__ bias, const float* __restrict__ R,
    float* __restrict__ C, __nv_bfloat16* __restrict__ Chi,
    __nv_bfloat16* __restrict__ Clo, int M, int N, int K) {
    extern __shared__ char smem[];
    const uint32_t sb = smem_u32(smem);
    const int tid = threadIdx.x;
    const int lane = tid & 31;
    const int w = tid >> 5;
    const int wm = w >> 2;        // 0..1
    const int wn = w & 3;         // 0..3
    const int bm = blockIdx.y * 128;
    const int bn = blockIdx.x * 128;

    const int n_iter = K >> 6;
    const int frow = tid >> 3;    // 0..31 (+32 per t)
    const int fch = tid & 7;

    auto issue = [&](int it) {
        const int buf = it % NSTAGES;
        const int kt = it << 6;
        const uint32_t base = sb + buf * STAGE_B;
        #pragma unroll
        for (int t = 0; t < 4; ++t) {
            int row = frow + t * 32;
            uint32_t so = sw128((uint32_t)(row * 128 + fch * 16));
            size_t ga = (size_t)(bm + row) * K + kt + fch * 8;
            size_t gb = (size_t)(bn + row) * K + kt + fch * 8;
            CP_ASYNC16(base + so,              Ah + ga);
            CP_ASYNC16(base + TILE_B + so,     Al + ga);
            CP_ASYNC16(base + 2 * TILE_B + so, Bh + gb);
            CP_ASYNC16(base + 3 * TILE_B + so, Bl + gb);
        }
        CP_COMMIT();
    };

    float acc[4][4][4];
    #pragma unroll
    for (int mt = 0; mt < 4; ++mt)
        #pragma unroll
        for (int nt = 0; nt < 4; ++nt)
            #pragma unroll
            for (int e = 0; e < 4; ++e) acc[mt][nt][e] = 0.f;

    issue(0);
    if (n_iter > 1) issue(1);
    if (n_iter > 2) issue(2);

    // per-lane ldmatrix addresses (within a tile)
    const int a_row_base = wm * 64 + (lane & 15);
    const int a_cb = (lane >> 4) << 4;
    const int b_row_base = wn * 32 + (lane & 7) + ((lane >> 4) << 3);
    const int b_cb = ((lane >> 3) & 1) << 4;

    for (int it = 0; it < n_iter; ++it) {
        const int buf = it % NSTAGES;
        const int rem = n_iter - 1 - it;
        if (rem >= 2) { CP_WAIT2(); } else if (rem == 1) { CP_WAIT1(); } else { CP_WAIT0(); }
        __syncthreads();

        const uint32_t tAh = sb + buf * STAGE_B;
        const uint32_t tAl = tAh + TILE_B;
        const uint32_t tBh = tAh + 2 * TILE_B;
        const uint32_t tBl = tAh + 3 * TILE_B;

        #pragma unroll
        for (int ks = 0; ks < 4; ++ks) {
            uint32_t ah[4][4], al[4][4];
            #pragma unroll
            for (int mt = 0; mt < 4; ++mt) {
                uint32_t off = sw128((uint32_t)((a_row_base + mt * 16) * 128 + ks * 32 + a_cb));
                LDSM4(ah[mt][0], ah[mt][1], ah[mt][2], ah[mt][3], tAh + off);
                LDSM4(al[mt][0], al[mt][1], al[mt][2], al[mt][3], tAl + off);
            }
            uint32_t bh[2][4], bl[2][4];
            #pragma unroll
            for (int nt2 = 0; nt2 < 2; ++nt2) {
                uint32_t off = sw128((uint32_t)((b_row_base + nt2 * 16) * 128 + ks * 32 + b_cb));
                LDSM4(bh[nt2][0], bh[nt2][1], bh[nt2][2], bh[nt2][3], tBh + off);
                LDSM4(bl[nt2][0], bl[nt2][1], bl[nt2][2], bl[nt2][3], tBl + off);
            }
            #pragma unroll
            for (int mt = 0; mt < 4; ++mt)
                #pragma unroll
                for (int nt = 0; nt < 4; ++nt) {
                    uint32_t b0h = bh[nt >> 1][(nt & 1) * 2], b1h = bh[nt >> 1][(nt & 1) * 2 + 1];
                    uint32_t b0l = bl[nt >> 1][(nt & 1) * 2], b1l = bl[nt >> 1][(nt & 1) * 2 + 1];
                    mma16816(acc[mt][nt], ah[mt], b0h, b1h);
                    mma16816(acc[mt][nt], ah[mt], b0l, b1l);
                    mma16816(acc[mt][nt], al[mt], b0h, b1h);
                }
        }
        __syncthreads();
        if (it + NSTAGES < n_iter) issue(it + NSTAGES);
    }

    // epilogue
    const int r0 = lane >> 2;
    const int c0 = (lane & 3) * 2;
    #pragma unroll
    for (int mt = 0; mt < 4; ++mt) {
        #pragma unroll
        for (int rr = 0; rr < 2; ++rr) {
            size_t m = (size_t)(bm + wm * 64 + mt * 16 + r0 + rr * 8);
            #pragma unroll
            for (int nt = 0; nt < 4; ++nt) {
                int n = bn + wn * 32 + nt * 8 + c0;
                float2 bv = *(const float2*)(bias + n);
                float vx = acc[mt][nt][rr * 2 + 0] + bv.x;
                float vy = acc[mt][nt][rr * 2 + 1] + bv.y;
                if (RES) {
                    float2 rv = *(const float2*)(R + m * N + n);
                    vx += rv.x; vy += rv.y;
                }
                if (RELU) { vx = fmaxf(vx, 0.f); vy = fmaxf(vy, 0.f); }
                if (SPLIT) {
                    __nv_bfloat16 hx = __float2bfloat16(vx);
                    __nv_bfloat16 hy = __float2bfloat16(vy);
                    __nv_bfloat16 lx = __float2bfloat16(vx - __bfloat162float(hx));
                    __nv_bfloat16 ly = __float2bfloat16(vy - __bfloat162float(hy));
                    *(__nv_bfloat162*)(Chi + m * N + n) = __nv_bfloat162(hx, hy);
                    *(__nv_bfloat162*)(Clo + m * N + n) = __nv_bfloat162(lx, ly);
                } else {
                    *(float2*)(C + m * N + n) = make_float2(vx, vy);
                }
            }
        }
    }
}

// ---------------- weight transpose + split: W[K,N] fp32 -> WT[N,K] bf16 hi/lo ----
__global__ void wsplit_kernel(const float* __restrict__ W, __nv_bfloat16* __restrict__ Th,
                              __nv_bfloat16* __restrict__ Tl, int K, int N) {
    __shared__ float t[32][33];
    int n0 = blockIdx.x * 32, k0 = blockIdx.y * 32;
    int tx = threadIdx.x, ty = threadIdx.y;
    #pragma unroll
    for (int i = ty; i < 32; i += 8)
        t[i][tx] = W[(size_t)(k0 + i) * N + n0 + tx];
    __syncthreads();
    #pragma unroll
    for (int i = ty; i < 32; i += 8) {
        float v = t[tx][i];
        __nv_bfloat16 h = __float2bfloat16(v);
        __nv_bfloat16 l = __float2bfloat16(v - __bfloat162float(h));
        size_t o = (size_t)(n0 + i) * K + k0 + tx;
        Th[o] = h;
        Tl[o] = l;
    }
}

// ---------------- bias concat (bq|bk|bv -> 3072) ----------------
__global__ void concat3_kernel(const float* __restrict__ a, const float* __restrict__ b,
                               const float* __restrict__ c, float* __restrict__ o) {
    int i = blockIdx.x * 256 + threadIdx.x;
    if (i < 1024) o[i] = a[i];
    else if (i < 2048) o[i] = b[i - 1024];
    else if (i < 3072) o[i] = c[i - 2048];
}

// ---------------- LayerNorm -> bf16 hi/lo split ----------------
__global__ void ln_split_kernel(const float* __restrict__ x, const float* __restrict__ gam,
                                const float* __restrict__ bet,
                                __nv_bfloat16* __restrict__ hi, __nv_bfloat16* __restrict__ lo) {
    int row = blockIdx.x;
    const float* xr = x + (size_t)row * D_MODEL;
    int tid = threadIdx.x;
    float4 v = *(const float4*)(xr + tid * 4);
    float s  = v.x + v.y + v.z + v.w;
    float ss = v.x * v.x + v.y * v.y + v.z * v.z + v.w * v.w;
    #pragma unroll
    for (int o = 16; o > 0; o >>= 1) {
        s  += __shfl_xor_sync(0xffffffffu, s, o);
        ss += __shfl_xor_sync(0xffffffffu, ss, o);
    }
    __shared__ float sh[16];
    int wid = tid >> 5, lane = tid & 31;
    if (lane == 0) { sh[wid] = s; sh[8 + wid] = ss; }
    __syncthreads();
    if (tid == 0) {
        float a = 0.f, b = 0.f;
        #pragma unroll
        for (int w = 0; w < 8; ++w) { a += sh[w]; b += sh[8 + w]; }
        sh[0] = a; sh[8] = b;
    }
    __syncthreads();
    float mu  = sh[0] * (1.0f / D_MODEL);
    float var = sh[8] * (1.0f / D_MODEL) - mu * mu;
    float r = rsqrtf(var + 1e-5f);
    float4 gv = *(const float4*)(gam + tid * 4);
    float4 bv = *(const float4*)(bet + tid * 4);
    float o4[4];
    o4[0] = (v.x - mu) * r * gv.x + bv.x;
    o4[1] = (v.y - mu) * r * gv.y + bv.y;
    o4[2] = (v.z - mu) * r * gv.z + bv.z;
    o4[3] = (v.w - mu) * r * gv.w + bv.w;
    __nv_bfloat16 h4[4], l4[4];
    #pragma unroll
    for (int j = 0; j < 4; ++j) {
        h4[j] = __float2bfloat16(o4[j]);
        l4[j] = __float2bfloat16(o4[j] - __bfloat162float(h4[j]));
    }
    size_t base = (size_t)row * D_MODEL + tid * 4;
    __nv_bfloat162* ph = (__nv_bfloat162*)(hi + base);
    __nv_bfloat162* pl = (__nv_bfloat162*)(lo + base);
    ph[0] = __nv_bfloat162(h4[0], h4[1]); ph[1] = __nv_bfloat162(h4[2], h4[3]);
    pl[0] = __nv_bfloat162(l4[0], l4[1]); pl[1] = __nv_bfloat162(l4[2], l4[3]);
}

// ---------------- Flash attention (fp32) over packed QKV; emits ctx hi/lo -------
#define AQ 64
#define AKV 64
#define APAD 65
#define ATTN_SMEM_FLOATS (4 * AQ * APAD + AKV)

__global__ void __launch_bounds__(128) attn_kernel(
    const float* __restrict__ QKV, const int* __restrict__ mask,
    __nv_bfloat16* __restrict__ Ohi, __nv_bfloat16* __restrict__ Olo) {
    extern __shared__ float sm[];
    float (*Qs)[APAD] = (float(*)[APAD])(sm);
    float (*Ks)[APAD] = (float(*)[APAD])(sm + AQ * APAD);
    float (*Vs)[APAD] = (float(*)[APAD])(sm + 2 * AQ * APAD);
    float (*Ps)[APAD] = (float(*)[APAD])(sm + 3 * AQ * APAD);
    float* Ms = sm + 4 * AQ * APAD;

    int tid = threadIdx.x;
    int q0 = blockIdx.x * AQ;
    int b = blockIdx.y >> 4;
    int h = blockIdx.y & 15;
    const float scale = 0.125f;

    const float* Qb = QKV + ((size_t)(b * SEQ + q0)) * QKV_N + h * D_HEAD;
    const float* Kb = QKV + ((size_t)(b * SEQ)) * QKV_N + 1024 + h * D_HEAD;
    const float* Vb = QKV + ((size_t)(b * SEQ)) * QKV_N + 2048 + h * D_HEAD;

    for (int idx = tid; idx < AQ * 16; idx += 128) {
        int r = idx >> 4, c4 = (idx & 15) << 2;
        float4 v = *(const float4*)(Qb + (size_t)r * QKV_N + c4);
        Qs[r][c4 + 0] = v.x * scale;
        Qs[r][c4 + 1] = v.y * scale;
        Qs[r][c4 + 2] = v.z * scale;
        Qs[r][c4 + 3] = v.w * scale;
    }

    int ty = tid >> 3, tx = tid & 7;
    int r0 = ty * 4;
    float m_i[4] = {-1e30f, -1e30f, -1e30f, -1e30f};
    float l_i[4] = {0.f, 0.f, 0.f, 0.f};
    float acc[4][8];
    #pragma unroll
    for (int i = 0; i < 4; ++i)
        #pragma unroll
        for (int j = 0; j < 8; ++j) acc[i][j] = 0.f;

    for (int kt = 0; kt < SEQ; kt += AKV) {
        __syncthreads();
        for (int idx = tid; idx < AKV * 16; idx += 128) {
            int r = idx >> 4, c4 = (idx & 15) << 2;
            float4 kv = *(const float4*)(Kb + (size_t)(kt + r) * QKV_N + c4);
            Ks[r][c4 + 0] = kv.x; Ks[r][c4 + 1] = kv.y;
            Ks[r][c4 + 2] = kv.z; Ks[r][c4 + 3] = kv.w;
            float4 vv = *(const float4*)(Vb + (size_t)(kt + r) * QKV_N + c4);
            Vs[r][c4 + 0] = vv.x; Vs[r][c4 + 1] = vv.y;
            Vs[r][c4 + 2] = vv.z; Vs[r][c4 + 3] = vv.w;
        }
        if (tid < AKV) Ms[tid] = (mask[b * SEQ + kt + tid] == 0) ? -1e30f : 0.0f;
        __syncthreads();

        float s[4][8];
        #pragma unroll
        for (int i = 0; i < 4; ++i)
            #pragma unroll
            for (int j = 0; j < 8; ++j) s[i][j] = 0.f;
        #pragma unroll 8
        for (int d = 0; d < D_HEAD; ++d) {
            float kr[8];
            #pragma unroll
            for (int j = 0; j < 8; ++j) kr[j] = Ks[tx + 8 * j][d];
            #pragma unroll
            for (int i = 0; i < 4; ++i) {
                float qv = Qs[r0 + i][d];
                #pragma unroll
                for (int j = 0; j < 8; ++j) s[i][j] = fmaf(qv, kr[j], s[i][j]);
            }
        }
        #pragma unroll
        for (int j = 0; j < 8; ++j) {
            float mv = Ms[tx + 8 * j];
            #pragma unroll
            for (int i = 0; i < 4; ++i) s[i][j] += mv;
        }
        #pragma unroll
        for (int i = 0; i < 4; ++i) {
            float mloc = s[i][0];
            #pragma unroll
            for (int j = 1; j < 8; ++j) mloc = fmaxf(mloc, s[i][j]);
            #pragma unroll
            for (int o = 1; o < 8; o <<= 1)
                mloc = fmaxf(mloc, __shfl_xor_sync(0xffffffffu, mloc, o));
            float mnew = fmaxf(m_i[i], mloc);
            float alpha = __expf(m_i[i] - mnew);
            float lsum = 0.f;
            #pragma unroll
            for (int j = 0; j < 8; ++j) {
                float p = __expf(s[i][j] - mnew);
                s[i][j] = p;
                lsum += p;
            }
            #pragma unroll
            for (int o = 1; o < 8; o <<= 1)
                lsum += __shfl_xor_sync(0xffffffffu, lsum, o);
            l_i[i] = l_i[i] * alpha + lsum;
            m_i[i] = mnew;
            #pragma unroll
            for (int j = 0; j < 8; ++j) acc[i][j] *= alpha;
            #pragma unroll
            for (int j = 0; j < 8; ++j) Ps[r0 + i][tx + 8 * j] = s[i][j];
        }
        __syncthreads();

        #pragma unroll 4
        for (int j = 0; j < AKV; ++j) {
            float vr[8];
            #pragma unroll
            for (int jj = 0; jj < 8; ++jj) vr[jj] = Vs[j][tx + 8 * jj];
            #pragma unroll
            for (int i = 0; i < 4; ++i) {
                float p = Ps[r0 + i][j];
                #pragma unroll
                for (int jj = 0; jj < 8; ++jj)
                    acc[i][jj] = fmaf(p, vr[jj], acc[i][jj]);
            }
        }
    }

    size_t obase = ((size_t)(b * SEQ + q0)) * D_MODEL + h * D_HEAD;
    #pragma unroll
    for (int i = 0; i < 4; ++i) {
        float inv = 1.0f / l_i[i];
        #pragma unroll
        for (int jj = 0; jj < 8; ++jj) {
            float o = acc[i][jj] * inv;
            __nv_bfloat16 hv = __float2bfloat16(o);
            size_t idx = obase + (size_t)(r0 + i) * D_MODEL + tx + 8 * jj;
            Ohi[idx] = hv;
            Olo[idx] = __float2bfloat16(o - __bfloat162float(hv));
        }
    }
}

// ---------------- launch ----------------
extern "C" void kernel_launch(void* const* d_in, const int* in_sizes, int n_in,
                              void* d_out, int out_size) {
    const float* x     = (const float*)d_in[0];
    const int*   mask  = (const int*)d_in[1];
    const float* wq    = (const float*)d_in[2];
    const float* bq    = (const float*)d_in[3];
    const float* wk    = (const float*)d_in[4];
    const float* bk    = (const float*)d_in[5];
    const float* wv    = (const float*)d_in[6];
    const float* bv    = (const float*)d_in[7];
    const float* wo    = (const float*)d_in[8];
    const float* bo    = (const float*)d_in[9];
    const float* ln1_g = (const float*)d_in[10];
    const float* ln1_b = (const float*)d_in[11];
    const float* ln2_g = (const float*)d_in[12];
    const float* ln2_b = (const float*)d_in[13];
    const float* w1    = (const float*)d_in[14];
    const float* b1    = (const float*)d_in[15];
    const float* w2    = (const float*)d_in[16];
    const float* b2    = (const float*)d_in[17];
    float* out = (float*)d_out;

    float *qkv, *x1, *bqkv;
    __nv_bfloat16 *ah, *al, *fh, *fl, *wh, *wl;
    cudaGetSymbolAddress((void**)&qkv,  g_qkv);
    cudaGetSymbolAddress((void**)&x1,   g_x1);
    cudaGetSymbolAddress((void**)&bqkv, g_bqkv);
    cudaGetSymbolAddress((void**)&ah,   s_ah);
    cudaGetSymbolAddress((void**)&al,   s_al);
    cudaGetSymbolAddress((void**)&fh,   s_fh);
    cudaGetSymbolAddress((void**)&fl,   s_fl);
    cudaGetSymbolAddress((void**)&wh,   s_wh);
    cudaGetSymbolAddress((void**)&wl,   s_wl);

    cudaFuncSetAttribute(mma_gemm<false, false, false>, cudaFuncAttributeMaxDynamicSharedMemorySize, GSMEM_TOTAL);
    cudaFuncSetAttribute(mma_gemm<false, true, false>,  cudaFuncAttributeMaxDynamicSharedMemorySize, GSMEM_TOTAL);
    cudaFuncSetAttribute(mma_gemm<true, false, true>,   cudaFuncAttributeMaxDynamicSharedMemorySize, GSMEM_TOTAL);
    static const int attn_smem = ATTN_SMEM_FLOATS * (int)sizeof(float);
    cudaFuncSetAttribute(attn_kernel, cudaFuncAttributeMaxDynamicSharedMemorySize, attn_smem);

    dim3 wsb(32, 8);

    // --- residual 1 ---
    ln_split_kernel<<<NTOK, 256>>>(x, ln1_g, ln1_b, ah, al);
    wsplit_kernel<<<dim3(32, 32), wsb>>>(wq, wh, wl, D_MODEL, D_MODEL);
    wsplit_kernel<<<dim3(32, 32), wsb>>>(wk, wh + 1024 * 1024, wl + 1024 * 1024, D_MODEL, D_MODEL);
    wsplit_kernel<<<dim3(32, 32), wsb>>>(wv, wh + 2 * 1024 * 1024, wl + 2 * 1024 * 1024, D_MODEL, D_MODEL);
    concat3_kernel<<<12, 256>>>(bq, bk, bv, bqkv);

    mma_gemm<false, false, false><<<dim3(QKV_N / 128, NTOK / 128), 256, GSMEM_TOTAL>>>(
        ah, al, wh, wl, bqkv, nullptr, qkv, nullptr, nullptr, NTOK, QKV_N, D_MODEL);

    attn_kernel<<<dim3(SEQ / AQ, BATCH * N_HEADS), 128, attn_smem>>>(qkv, mask, ah, al);

    wsplit_kernel<<<dim3(32, 32), wsb>>>(wo, wh, wl, D_MODEL, D_MODEL);
    mma_gemm<false, true, false><<<dim3(D_MODEL / 128, NTOK / 128), 256, GSMEM_TOTAL>>>(
        ah, al, wh, wl, bo, x, x1, nullptr, nullptr, NTOK, D_MODEL, D_MODEL);

    // --- residual 2 ---
    ln_split_kernel<<<NTOK, 256>>>(x1, ln2_g, ln2_b, ah, al);
    wsplit_kernel<<<dim3(FF_DIM / 32, D_MODEL / 32), wsb>>>(w1, wh, wl, D_MODEL, FF_DIM);
    mma_gemm<true, false, true><<<dim3(FF_DIM / 128, NTOK / 128), 256, GSMEM_TOTAL>>>(
        ah, al, wh, wl, b1, nullptr, nullptr, fh, fl, NTOK, FF_DIM, D_MODEL);

    wsplit_kernel<<<dim3(D_MODEL / 32, FF_DIM / 32), wsb>>>(w2, wh, wl, FF_DIM, D_MODEL);
    mma_gemm<false, true, false><<<dim3(D_MODEL / 128, NTOK / 128), 256, GSMEM_TOTAL>>>(
        fh, fl, wh, wl, b2, x1, out, nullptr, nullptr, NTOK, D_MODEL, FF_DIM);
}

// round 6
// speedup vs baseline: 3.1205x; 1.6493x over previous
#include <cuda_runtime.h>
#include <cuda_bf16.h>
#include <cstdint>
#include <math.h>

#define D_MODEL 1024
#define N_HEADS 16
#define D_HEAD 64
#define FF_DIM 4096
#define SEQ 2048
#define BATCH 2
#define NTOK (BATCH * SEQ)  // 4096
#define QKV_N 3072

// ---------------- scratch (static device arrays; no allocations) ----------------
__device__ float g_x1[NTOK * D_MODEL];
__device__ float g_bqkv[QKV_N];
__device__ __nv_bfloat16 s_ah[NTOK * D_MODEL];   // LN out / ctx hi
__device__ __nv_bfloat16 s_al[NTOK * D_MODEL];
__device__ __nv_bfloat16 s_fh[NTOK * FF_DIM];    // qkv hi, later FF hidden hi
__device__ __nv_bfloat16 s_fl[NTOK * FF_DIM];
__device__ __nv_bfloat16 s_wh[FF_DIM * D_MODEL];
__device__ __nv_bfloat16 s_wl[FF_DIM * D_MODEL];

// ======================= PTX helpers (sm_80-compatible) =======================
__device__ __forceinline__ uint32_t smem_u32(const void* p) {
    uint32_t a;
    asm("{ .reg .u64 t; cvta.to.shared.u64 t, %1; cvt.u32.u64 %0, t; }" : "=r"(a) : "l"(p));
    return a;
}
#define CP_ASYNC16(dst, src) \
    asm volatile("cp.async.cg.shared.global [%0], [%1], 16;" :: "r"(dst), "l"(src))
#define CP_COMMIT() asm volatile("cp.async.commit_group;" ::: "memory")
#define CP_WAIT2() asm volatile("cp.async.wait_group 2;" ::: "memory")
#define CP_WAIT1() asm volatile("cp.async.wait_group 1;" ::: "memory")
#define CP_WAIT0() asm volatile("cp.async.wait_group 0;" ::: "memory")

#define LDSM4(r0, r1, r2, r3, addr) \
    asm volatile("ldmatrix.sync.aligned.m8n8.x4.shared.b16 {%0,%1,%2,%3}, [%4];" \
                 : "=r"(r0), "=r"(r1), "=r"(r2), "=r"(r3) : "r"(addr))

__device__ __forceinline__ void mma16816(float* d, const uint32_t* a,
                                         uint32_t b0, uint32_t b1) {
    asm volatile(
        "mma.sync.aligned.m16n8k16.row.col.f32.bf16.bf16.f32 "
        "{%0,%1,%2,%3}, {%4,%5,%6,%7}, {%8,%9}, {%0,%1,%2,%3};"
        : "+f"(d[0]), "+f"(d[1]), "+f"(d[2]), "+f"(d[3])
        : "r"(a[0]), "r"(a[1]), "r"(a[2]), "r"(a[3]), "r"(b0), "r"(b1));
}

__device__ __forceinline__ uint32_t sw128(uint32_t off) {
    return off ^ ((off >> 3) & 0x70);
}
__device__ __forceinline__ uint32_t pack_bf16(float x, float y) {
    __nv_bfloat162 t;
    t.x = __float2bfloat16(x);
    t.y = __float2bfloat16(y);
    return *reinterpret_cast<uint32_t*>(&t);
}

// ======================= bf16x3 tensor-core GEMM (merged segments) ============
#define TILE_B 16384
#define STAGE_B (4 * TILE_B)
#define NSTAGES 3
#define GSMEM_TOTAL (NSTAGES * STAGE_B)   // 192 KB

template <bool RELU, bool RES, bool SPLIT>
__global__ void __launch_bounds__(256, 1) mma_gemm(
    const __nv_bfloat16* __restrict__ Ah, const __nv_bfloat16* __restrict__ Al,
    const __nv_bfloat16* __restrict__ Bh, const __nv_bfloat16* __restrict__ Bl,
    const float* __restrict__ bias, const float* __restrict__ R,
    float* __restrict__ C, __nv_bfloat16* __restrict__ Chi,
    __nv_bfloat16* __restrict__ Clo, int M, int N, int K) {
    extern __shared__ char smem[];
    const uint32_t sb = smem_u32(smem);
    const int tid = threadIdx.x;
    const int lane = tid & 31;
    const int w = tid >> 5;
    const int wm = w >> 2;
    const int wn = w & 3;
    const int bm = blockIdx.y * 128;
    const int bn = blockIdx.x * 128;

    const int n_iter = K >> 6;
    const int frow = tid >> 3;
    const int fch = tid & 7;

    auto issue = [&](int it) {
        const int buf = it % NSTAGES;
        const int kt = it << 6;
        const uint32_t base = sb + buf * STAGE_B;
        #pragma unroll
        for (int t = 0; t < 4; ++t) {
            int row = frow + t * 32;
            uint32_t so = sw128((uint32_t)(row * 128 + fch * 16));
            size_t ga = (size_t)(bm + row) * K + kt + fch * 8;
            size_t gb = (size_t)(bn + row) * K + kt + fch * 8;
            CP_ASYNC16(base + so,              Ah + ga);
            CP_ASYNC16(base + TILE_B + so,     Al + ga);
            CP_ASYNC16(base + 2 * TILE_B + so, Bh + gb);
            CP_ASYNC16(base + 3 * TILE_B + so, Bl + gb);
        }
        CP_COMMIT();
    };

    float acc[4][4][4];
    #pragma unroll
    for (int mt = 0; mt < 4; ++mt)
        #pragma unroll
        for (int nt = 0; nt < 4; ++nt)
            #pragma unroll
            for (int e = 0; e < 4; ++e) acc[mt][nt][e] = 0.f;

    issue(0);
    if (n_iter > 1) issue(1);
    if (n_iter > 2) issue(2);

    const int a_row_base = wm * 64 + (lane & 15);
    const int a_cb = (lane >> 4) << 4;
    const int b_row_base = wn * 32 + (lane & 7) + ((lane >> 4) << 3);
    const int b_cb = ((lane >> 3) & 1) << 4;

    for (int it = 0; it < n_iter; ++it) {
        const int buf = it % NSTAGES;
        const int rem = n_iter - 1 - it;
        if (rem >= 2) { CP_WAIT2(); } else if (rem == 1) { CP_WAIT1(); } else { CP_WAIT0(); }
        __syncthreads();

        const uint32_t tAh = sb + buf * STAGE_B;
        const uint32_t tAl = tAh + TILE_B;
        const uint32_t tBh = tAh + 2 * TILE_B;
        const uint32_t tBl = tAh + 3 * TILE_B;

        #pragma unroll
        for (int ks = 0; ks < 4; ++ks) {
            uint32_t ah[4][4], al[4][4];
            #pragma unroll
            for (int mt = 0; mt < 4; ++mt) {
                uint32_t off = sw128((uint32_t)((a_row_base + mt * 16) * 128 + ks * 32 + a_cb));
                LDSM4(ah[mt][0], ah[mt][1], ah[mt][2], ah[mt][3], tAh + off);
                LDSM4(al[mt][0], al[mt][1], al[mt][2], al[mt][3], tAl + off);
            }
            uint32_t bh[2][4], bl[2][4];
            #pragma unroll
            for (int nt2 = 0; nt2 < 2; ++nt2) {
                uint32_t off = sw128((uint32_t)((b_row_base + nt2 * 16) * 128 + ks * 32 + b_cb));
                LDSM4(bh[nt2][0], bh[nt2][1], bh[nt2][2], bh[nt2][3], tBh + off);
                LDSM4(bl[nt2][0], bl[nt2][1], bl[nt2][2], bl[nt2][3], tBl + off);
            }
            #pragma unroll
            for (int mt = 0; mt < 4; ++mt)
                #pragma unroll
                for (int nt = 0; nt < 4; ++nt) {
                    uint32_t b0h = bh[nt >> 1][(nt & 1) * 2], b1h = bh[nt >> 1][(nt & 1) * 2 + 1];
                    uint32_t b0l = bl[nt >> 1][(nt & 1) * 2], b1l = bl[nt >> 1][(nt & 1) * 2 + 1];
                    mma16816(acc[mt][nt], ah[mt], b0h, b1h);
                    mma16816(acc[mt][nt], ah[mt], b0l, b1l);
                    mma16816(acc[mt][nt], al[mt], b0h, b1h);
                }
        }
        __syncthreads();
        if (it + NSTAGES < n_iter) issue(it + NSTAGES);
    }

    const int r0 = lane >> 2;
    const int c0 = (lane & 3) * 2;
    #pragma unroll
    for (int mt = 0; mt < 4; ++mt) {
        #pragma unroll
        for (int rr = 0; rr < 2; ++rr) {
            size_t m = (size_t)(bm + wm * 64 + mt * 16 + r0 + rr * 8);
            #pragma unroll
            for (int nt = 0; nt < 4; ++nt) {
                int n = bn + wn * 32 + nt * 8 + c0;
                float2 bv = *(const float2*)(bias + n);
                float vx = acc[mt][nt][rr * 2 + 0] + bv.x;
                float vy = acc[mt][nt][rr * 2 + 1] + bv.y;
                if (RES) {
                    float2 rv = *(const float2*)(R + m * N + n);
                    vx += rv.x; vy += rv.y;
                }
                if (RELU) { vx = fmaxf(vx, 0.f); vy = fmaxf(vy, 0.f); }
                if (SPLIT) {
                    __nv_bfloat16 hx = __float2bfloat16(vx);
                    __nv_bfloat16 hy = __float2bfloat16(vy);
                    __nv_bfloat16 lx = __float2bfloat16(vx - __bfloat162float(hx));
                    __nv_bfloat16 ly = __float2bfloat16(vy - __bfloat162float(hy));
                    *(__nv_bfloat162*)(Chi + m * N + n) = __nv_bfloat162(hx, hy);
                    *(__nv_bfloat162*)(Clo + m * N + n) = __nv_bfloat162(lx, ly);
                } else {
                    *(float2*)(C + m * N + n) = make_float2(vx, vy);
                }
            }
        }
    }
}

// ---------------- weight transpose + split ----------------
__global__ void wsplit_kernel(const float* __restrict__ W, __nv_bfloat16* __restrict__ Th,
                              __nv_bfloat16* __restrict__ Tl, int K, int N) {
    __shared__ float t[32][33];
    int n0 = blockIdx.x * 32, k0 = blockIdx.y * 32;
    int tx = threadIdx.x, ty = threadIdx.y;
    #pragma unroll
    for (int i = ty; i < 32; i += 8)
        t[i][tx] = W[(size_t)(k0 + i) * N + n0 + tx];
    __syncthreads();
    #pragma unroll
    for (int i = ty; i < 32; i += 8) {
        float v = t[tx][i];
        __nv_bfloat16 h = __float2bfloat16(v);
        __nv_bfloat16 l = __float2bfloat16(v - __bfloat162float(h));
        size_t o = (size_t)(n0 + i) * K + k0 + tx;
        Th[o] = h;
        Tl[o] = l;
    }
}

__global__ void concat3_kernel(const float* __restrict__ a, const float* __restrict__ b,
                               const float* __restrict__ c, float* __restrict__ o) {
    int i = blockIdx.x * 256 + threadIdx.x;
    if (i < 1024) o[i] = a[i];
    else if (i < 2048) o[i] = b[i - 1024];
    else if (i < 3072) o[i] = c[i - 2048];
}

// ---------------- LayerNorm -> bf16 hi/lo split ----------------
__global__ void ln_split_kernel(const float* __restrict__ x, const float* __restrict__ gam,
                                const float* __restrict__ bet,
                                __nv_bfloat16* __restrict__ hi, __nv_bfloat16* __restrict__ lo) {
    int row = blockIdx.x;
    const float* xr = x + (size_t)row * D_MODEL;
    int tid = threadIdx.x;
    float4 v = *(const float4*)(xr + tid * 4);
    float s  = v.x + v.y + v.z + v.w;
    float ss = v.x * v.x + v.y * v.y + v.z * v.z + v.w * v.w;
    #pragma unroll
    for (int o = 16; o > 0; o >>= 1) {
        s  += __shfl_xor_sync(0xffffffffu, s, o);
        ss += __shfl_xor_sync(0xffffffffu, ss, o);
    }
    __shared__ float sh[16];
    int wid = tid >> 5, lane = tid & 31;
    if (lane == 0) { sh[wid] = s; sh[8 + wid] = ss; }
    __syncthreads();
    if (tid == 0) {
        float a = 0.f, b = 0.f;
        #pragma unroll
        for (int w = 0; w < 8; ++w) { a += sh[w]; b += sh[8 + w]; }
        sh[0] = a; sh[8] = b;
    }
    __syncthreads();
    float mu  = sh[0] * (1.0f / D_MODEL);
    float var = sh[8] * (1.0f / D_MODEL) - mu * mu;
    float r = rsqrtf(var + 1e-5f);
    float4 gv = *(const float4*)(gam + tid * 4);
    float4 bv = *(const float4*)(bet + tid * 4);
    float o4[4];
    o4[0] = (v.x - mu) * r * gv.x + bv.x;
    o4[1] = (v.y - mu) * r * gv.y + bv.y;
    o4[2] = (v.z - mu) * r * gv.z + bv.z;
    o4[3] = (v.w - mu) * r * gv.w + bv.w;
    __nv_bfloat16 h4[4], l4[4];
    #pragma unroll
    for (int j = 0; j < 4; ++j) {
        h4[j] = __float2bfloat16(o4[j]);
        l4[j] = __float2bfloat16(o4[j] - __bfloat162float(h4[j]));
    }
    size_t base = (size_t)row * D_MODEL + tid * 4;
    __nv_bfloat162* ph = (__nv_bfloat162*)(hi + base);
    __nv_bfloat162* pl = (__nv_bfloat162*)(lo + base);
    ph[0] = __nv_bfloat162(h4[0], h4[1]); ph[1] = __nv_bfloat162(h4[2], h4[3]);
    pl[0] = __nv_bfloat162(l4[0], l4[1]); pl[1] = __nv_bfloat162(l4[2], l4[3]);
}

// =============== tensor-core flash attention (bf16x3 QK, bf16 PV) =============
// Q-tile 128 x KV-tile 64, 8 warps (16 q rows each). QKV packed bf16 hi/lo.
// smem offsets (all 1024-aligned)
#define SQH 0
#define SQL 16384
#define SKH(b) (32768 + (b) * 24576)
#define SKL(b) (32768 + (b) * 24576 + 8192)
#define SVS(b) (32768 + (b) * 24576 + 16384)
#define SVT 81920
#define SMSK(b) (90112 + (b) * 256)
#define ASMEM 90624
#define NKV (SEQ / 64)   // 32

__global__ void __launch_bounds__(256, 1) attn_tc_kernel(
    const __nv_bfloat16* __restrict__ QKVh, const __nv_bfloat16* __restrict__ QKVl,
    const int* __restrict__ mask,
    __nv_bfloat16* __restrict__ Ohi, __nv_bfloat16* __restrict__ Olo) {
    extern __shared__ char smem[];
    const uint32_t sb = smem_u32(smem);
    const int tid = threadIdx.x;
    const int lane = tid & 31;
    const int w = tid >> 5;
    const int q0 = blockIdx.x * 128;
    const int b = blockIdx.y >> 4;
    const int h = blockIdx.y & 15;
    const size_t tok0 = (size_t)b * SEQ;

    const __nv_bfloat16* Qh_g = QKVh + (tok0 + q0) * QKV_N + h * 64;
    const __nv_bfloat16* Ql_g = QKVl + (tok0 + q0) * QKV_N + h * 64;
    const __nv_bfloat16* Kh_g = QKVh + tok0 * QKV_N + 1024 + h * 64;
    const __nv_bfloat16* Kl_g = QKVl + tok0 * QKV_N + 1024 + h * 64;
    const __nv_bfloat16* Vh_g = QKVh + tok0 * QKV_N + 2048 + h * 64;
    const int* mask_b = mask + b * SEQ;

    auto issue_tile = [&](int t) {
        const int buf = t & 1;
        const int row = tid >> 2;          // 0..63
        const int ch0 = (tid & 3) * 2;
        const size_t roff = (size_t)(t * 64 + row) * QKV_N;
        #pragma unroll
        for (int c = 0; c < 2; ++c) {
            const int ch = ch0 + c;
            const uint32_t so = sw128((uint32_t)(row * 128 + ch * 16));
            CP_ASYNC16(sb + SKH(buf) + so, Kh_g + roff + ch * 8);
            CP_ASYNC16(sb + SKL(buf) + so, Kl_g + roff + ch * 8);
            CP_ASYNC16(sb + SVS(buf) + so, Vh_g + roff + ch * 8);
        }
        if (tid < 16) CP_ASYNC16(sb + SMSK(buf) + tid * 16, mask_b + t * 64 + tid * 4);
        CP_COMMIT();
    };

    // prologue: Q tile (hi+lo) in group 0 together with KV tile 0
    {
        const int row = tid >> 1;          // 0..127
        const int chb = (tid & 1) * 4;
        #pragma unroll
        for (int c = 0; c < 4; ++c) {
            const int ch = chb + c;
            const uint32_t so = sw128((uint32_t)(row * 128 + ch * 16));
            CP_ASYNC16(sb + SQH + so, Qh_g + (size_t)row * QKV_N + ch * 8);
            CP_ASYNC16(sb + SQL + so, Ql_g + (size_t)row * QKV_N + ch * 8);
        }
    }
    issue_tile(0);
    issue_tile(1);

    const int a_row = 16 * w + (lane & 15);
    const int a_cb = (lane >> 4) << 4;
    const int b_row = (lane & 7) + ((lane >> 4) << 3);
    const int b_cb = ((lane >> 3) & 1) << 4;

    float m0 = -1e30f, m1 = -1e30f, l0 = 0.f, l1 = 0.f;
    float ctx[8][4];
    #pragma unroll
    for (int dt = 0; dt < 8; ++dt)
        #pragma unroll
        for (int e = 0; e < 4; ++e) ctx[dt][e] = 0.f;

    for (int t = 0; t < NKV; ++t) {
        const int buf = t & 1;
        if (t == NKV - 1) { CP_WAIT0(); } else { CP_WAIT1(); }
        __syncthreads();   // KV tile t ready; all warps done with PV(t-1) -> Vt writable

        // ---- S = Q K^T (bf16x3) ----
        float s[8][4];
        #pragma unroll
        for (int nt = 0; nt < 8; ++nt)
            #pragma unroll
            for (int e = 0; e < 4; ++e) s[nt][e] = 0.f;

        #pragma unroll
        for (int ks = 0; ks < 4; ++ks) {
            uint32_t ah[4], al[4];
            {
                const uint32_t off = sw128((uint32_t)(a_row * 128 + ks * 32 + a_cb));
                LDSM4(ah[0], ah[1], ah[2], ah[3], sb + SQH + off);
                LDSM4(al[0], al[1], al[2], al[3], sb + SQL + off);
            }
            #pragma unroll
            for (int g = 0; g < 4; ++g) {
                uint32_t bh[4], bl[4];
                const uint32_t off = sw128((uint32_t)((g * 16 + b_row) * 128 + ks * 32 + b_cb));
                LDSM4(bh[0], bh[1], bh[2], bh[3], sb + SKH(buf) + off);
                LDSM4(bl[0], bl[1], bl[2], bl[3], sb + SKL(buf) + off);
                mma16816(s[2 * g],     ah, bh[0], bh[1]);
                mma16816(s[2 * g],     al, bh[0], bh[1]);
                mma16816(s[2 * g],     ah, bl[0], bl[1]);
                mma16816(s[2 * g + 1], ah, bh[2], bh[3]);
                mma16816(s[2 * g + 1], al, bh[2], bh[3]);
                mma16816(s[2 * g + 1], ah, bl[2], bl[3]);
            }
        }

        // ---- scale + mask + online softmax ----
        const int cbase = (lane & 3) * 2;
        float mx0 = -1e30f, mx1 = -1e30f;
        #pragma unroll
        for (int nt = 0; nt < 8; ++nt) {
            const int n0 = nt * 8 + cbase;
            const int mi0 = *(const int*)(smem + SMSK(buf) + n0 * 4);
            const int mi1 = *(const int*)(smem + SMSK(buf) + (n0 + 1) * 4);
            const float ad0 = (mi0 == 0) ? -1e30f : 0.f;
            const float ad1 = (mi1 == 0) ? -1e30f : 0.f;
            s[nt][0] = s[nt][0] * 0.125f + ad0;
            s[nt][1] = s[nt][1] * 0.125f + ad1;
            s[nt][2] = s[nt][2] * 0.125f + ad0;
            s[nt][3] = s[nt][3] * 0.125f + ad1;
            mx0 = fmaxf(mx0, fmaxf(s[nt][0], s[nt][1]));
            mx1 = fmaxf(mx1, fmaxf(s[nt][2], s[nt][3]));
        }
        mx0 = fmaxf(mx0, __shfl_xor_sync(0xffffffffu, mx0, 1));
        mx0 = fmaxf(mx0, __shfl_xor_sync(0xffffffffu, mx0, 2));
        mx1 = fmaxf(mx1, __shfl_xor_sync(0xffffffffu, mx1, 1));
        mx1 = fmaxf(mx1, __shfl_xor_sync(0xffffffffu, mx1, 2));
        const float mn0 = fmaxf(m0, mx0), mn1 = fmaxf(m1, mx1);
        const float al0 = __expf(m0 - mn0), al1 = __expf(m1 - mn1);
        float ls0 = 0.f, ls1 = 0.f;
        #pragma unroll
        for (int nt = 0; nt < 8; ++nt) {
            s[nt][0] = __expf(s[nt][0] - mn0); ls0 += s[nt][0];
            s[nt][1] = __expf(s[nt][1] - mn0); ls0 += s[nt][1];
            s[nt][2] = __expf(s[nt][2] - mn1); ls1 += s[nt][2];
            s[nt][3] = __expf(s[nt][3] - mn1); ls1 += s[nt][3];
        }
        ls0 += __shfl_xor_sync(0xffffffffu, ls0, 1);
        ls0 += __shfl_xor_sync(0xffffffffu, ls0, 2);
        ls1 += __shfl_xor_sync(0xffffffffu, ls1, 1);
        ls1 += __shfl_xor_sync(0xffffffffu, ls1, 2);
        l0 = l0 * al0 + ls0; l1 = l1 * al1 + ls1;
        m0 = mn0; m1 = mn1;
        #pragma unroll
        for (int dt = 0; dt < 8; ++dt) {
            ctx[dt][0] *= al0; ctx[dt][1] *= al0;
            ctx[dt][2] *= al1; ctx[dt][3] *= al1;
        }
        // pack P into A fragments (C-layout == A-layout, FA2 trick)
        uint32_t pA[4][4];
        #pragma unroll
        for (int j = 0; j < 4; ++j) {
            pA[j][0] = pack_bf16(s[2 * j][0],     s[2 * j][1]);
            pA[j][1] = pack_bf16(s[2 * j][2],     s[2 * j][3]);
            pA[j][2] = pack_bf16(s[2 * j + 1][0], s[2 * j + 1][1]);
            pA[j][3] = pack_bf16(s[2 * j + 1][2], s[2 * j + 1][3]);
        }

        // ---- transpose V stage [key][d] -> Vt [d][key] ----
        #pragma unroll
        for (int i = 0; i < 8; ++i) {
            const int linear = tid + i * 256;
            const int key = linear & 63;
            const int dp = linear >> 6;     // 0..31
            const uint32_t v = *(const uint32_t*)(smem + SVS(buf) + sw128((uint32_t)(key * 128 + dp * 4)));
            *(uint16_t*)(smem + SVT + sw128((uint32_t)((2 * dp) * 128 + key * 2)))     = (uint16_t)(v & 0xffff);
            *(uint16_t*)(smem + SVT + sw128((uint32_t)((2 * dp + 1) * 128 + key * 2))) = (uint16_t)(v >> 16);
        }
        __syncthreads();   // Vt ready; K/V stage [buf] fully consumed

        if (t + 2 < NKV) issue_tile(t + 2);

        // ---- ctx += P V ----
        #pragma unroll
        for (int j = 0; j < 4; ++j) {
            #pragma unroll
            for (int g = 0; g < 4; ++g) {
                uint32_t bv[4];
                const uint32_t off = sw128((uint32_t)((g * 16 + b_row) * 128 + j * 32 + b_cb));
                LDSM4(bv[0], bv[1], bv[2], bv[3], sb + SVT + off);
                mma16816(ctx[2 * g],     pA[j], bv[0], bv[1]);
                mma16816(ctx[2 * g + 1], pA[j], bv[2], bv[3]);
            }
        }
    }

    // ---- epilogue: normalize, split hi/lo, store ----
    const float inv0 = 1.0f / l0, inv1 = 1.0f / l1;
    const int row0 = q0 + 16 * w + (lane >> 2);
    #pragma unroll
    for (int dt = 0; dt < 8; ++dt) {
        const int d = h * 64 + dt * 8 + (lane & 3) * 2;
        float o0 = ctx[dt][0] * inv0, o1 = ctx[dt][1] * inv0;
        float o2 = ctx[dt][2] * inv1, o3 = ctx[dt][3] * inv1;
        __nv_bfloat16 h0 = __float2bfloat16(o0), h1b = __float2bfloat16(o1);
        __nv_bfloat16 h2 = __float2bfloat16(o2), h3 = __float2bfloat16(o3);
        size_t i0 = (tok0 + row0) * D_MODEL + d;
        size_t i1 = (tok0 + row0 + 8) * D_MODEL + d;
        *(__nv_bfloat162*)(Ohi + i0) = __nv_bfloat162(h0, h1b);
        *(__nv_bfloat162*)(Ohi + i1) = __nv_bfloat162(h2, h3);
        *(__nv_bfloat162*)(Olo + i0) = __nv_bfloat162(
            __float2bfloat16(o0 - __bfloat162float(h0)), __float2bfloat16(o1 - __bfloat162float(h1b)));
        *(__nv_bfloat162*)(Olo + i1) = __nv_bfloat162(
            __float2bfloat16(o2 - __bfloat162float(h2)), __float2bfloat16(o3 - __bfloat162float(h3)));
    }
}

// ---------------- launch ----------------
extern "C" void kernel_launch(void* const* d_in, const int* in_sizes, int n_in,
                              void* d_out, int out_size) {
    const float* x     = (const float*)d_in[0];
    const int*   mask  = (const int*)d_in[1];
    const float* wq    = (const float*)d_in[2];
    const float* bq    = (const float*)d_in[3];
    const float* wk    = (const float*)d_in[4];
    const float* bk    = (const float*)d_in[5];
    const float* wv    = (const float*)d_in[6];
    const float* bv    = (const float*)d_in[7];
    const float* wo    = (const float*)d_in[8];
    const float* bo    = (const float*)d_in[9];
    const float* ln1_g = (const float*)d_in[10];
    const float* ln1_b = (const float*)d_in[11];
    const float* ln2_g = (const float*)d_in[12];
    const float* ln2_b = (const float*)d_in[13];
    const float* w1    = (const float*)d_in[14];
    const float* b1    = (const float*)d_in[15];
    const float* w2    = (const float*)d_in[16];
    const float* b2    = (const float*)d_in[17];
    float* out = (float*)d_out;

    float *x1, *bqkv;
    __nv_bfloat16 *ah, *al, *fh, *fl, *wh, *wl;
    cudaGetSymbolAddress((void**)&x1,   g_x1);
    cudaGetSymbolAddress((void**)&bqkv, g_bqkv);
    cudaGetSymbolAddress((void**)&ah,   s_ah);
    cudaGetSymbolAddress((void**)&al,   s_al);
    cudaGetSymbolAddress((void**)&fh,   s_fh);
    cudaGetSymbolAddress((void**)&fl,   s_fl);
    cudaGetSymbolAddress((void**)&wh,   s_wh);
    cudaGetSymbolAddress((void**)&wl,   s_wl);

    cudaFuncSetAttribute(mma_gemm<false, false, true>, cudaFuncAttributeMaxDynamicSharedMemorySize, GSMEM_TOTAL);
    cudaFuncSetAttribute(mma_gemm<false, true, false>, cudaFuncAttributeMaxDynamicSharedMemorySize, GSMEM_TOTAL);
    cudaFuncSetAttribute(mma_gemm<true, false, true>,  cudaFuncAttributeMaxDynamicSharedMemorySize, GSMEM_TOTAL);
    cudaFuncSetAttribute(attn_tc_kernel, cudaFuncAttributeMaxDynamicSharedMemorySize, ASMEM);

    dim3 wsb(32, 8);

    // --- residual 1 ---
    ln_split_kernel<<<NTOK, 256>>>(x, ln1_g, ln1_b, ah, al);
    wsplit_kernel<<<dim3(32, 32), wsb>>>(wq, wh, wl, D_MODEL, D_MODEL);
    wsplit_kernel<<<dim3(32, 32), wsb>>>(wk, wh + 1024 * 1024, wl + 1024 * 1024, D_MODEL, D_MODEL);
    wsplit_kernel<<<dim3(32, 32), wsb>>>(wv, wh + 2 * 1024 * 1024, wl + 2 * 1024 * 1024, D_MODEL, D_MODEL);
    concat3_kernel<<<12, 256>>>(bq, bk, bv, bqkv);

    // fused QKV GEMM, bf16 hi/lo output (fh/fl reused as qkv hi/lo)
    mma_gemm<false, false, true><<<dim3(QKV_N / 128, NTOK / 128), 256, GSMEM_TOTAL>>>(
        ah, al, wh, wl, bqkv, nullptr, nullptr, fh, fl, NTOK, QKV_N, D_MODEL);

    // tensor-core flash attention -> ctx hi/lo in ah/al
    attn_tc_kernel<<<dim3(SEQ / 128, BATCH * N_HEADS), 256, ASMEM>>>(fh, fl, mask, ah, al);

    wsplit_kernel<<<dim3(32, 32), wsb>>>(wo, wh, wl, D_MODEL, D_MODEL);
    mma_gemm<false, true, false><<<dim3(D_MODEL / 128, NTOK / 128), 256, GSMEM_TOTAL>>>(
        ah, al, wh, wl, bo, x, x1, nullptr, nullptr, NTOK, D_MODEL, D_MODEL);

    // --- residual 2 ---
    ln_split_kernel<<<NTOK, 256>>>(x1, ln2_g, ln2_b, ah, al);
    wsplit_kernel<<<dim3(FF_DIM / 32, D_MODEL / 32), wsb>>>(w1, wh, wl, D_MODEL, FF_DIM);
    mma_gemm<true, false, true><<<dim3(FF_DIM / 128, NTOK / 128), 256, GSMEM_TOTAL>>>(
        ah, al, wh, wl, b1, nullptr, nullptr, fh, fl, NTOK, FF_DIM, D_MODEL);

    wsplit_kernel<<<dim3(D_MODEL / 32, FF_DIM / 32), wsb>>>(w2, wh, wl, FF_DIM, D_MODEL);
    mma_gemm<false, true, false><<<dim3(D_MODEL / 128, NTOK / 128), 256, GSMEM_TOTAL>>>(
        fh, fl, wh, wl, b2, x1, out, nullptr, nullptr, NTOK, D_MODEL, FF_DIM);
}

// round 7
// speedup vs baseline: 3.1700x; 1.0159x over previous
#include <cuda_runtime.h>
#include <cuda_bf16.h>
#include <cstdint>
#include <math.h>

#define D_MODEL 1024
#define N_HEADS 16
#define D_HEAD 64
#define FF_DIM 4096
#define SEQ 2048
#define BATCH 2
#define NTOK (BATCH * SEQ)  // 4096
#define QKV_N 3072

// ---------------- scratch (static device arrays; no allocations) ----------------
__device__ float g_x1[NTOK * D_MODEL];
__device__ float g_bqkv[QKV_N];
__device__ __nv_bfloat16 s_ah[NTOK * D_MODEL];   // LN out / ctx hi
__device__ __nv_bfloat16 s_al[NTOK * D_MODEL];
__device__ __nv_bfloat16 s_fh[NTOK * FF_DIM];    // qkv hi, later FF hidden hi
__device__ __nv_bfloat16 s_fl[NTOK * FF_DIM];
__device__ __nv_bfloat16 s_wh[FF_DIM * D_MODEL];
__device__ __nv_bfloat16 s_wl[FF_DIM * D_MODEL];

// ======================= PTX helpers (sm_80-compatible) =======================
__device__ __forceinline__ uint32_t smem_u32(const void* p) {
    uint32_t a;
    asm("{ .reg .u64 t; cvta.to.shared.u64 t, %1; cvt.u32.u64 %0, t; }" : "=r"(a) : "l"(p));
    return a;
}
#define CP_ASYNC16(dst, src) \
    asm volatile("cp.async.cg.shared.global [%0], [%1], 16;" :: "r"(dst), "l"(src))
#define CP_COMMIT() asm volatile("cp.async.commit_group;" ::: "memory")
#define CP_WAIT1() asm volatile("cp.async.wait_group 1;" ::: "memory")
#define CP_WAIT0() asm volatile("cp.async.wait_group 0;" ::: "memory")

#define LDSM4(r0, r1, r2, r3, addr) \
    asm volatile("ldmatrix.sync.aligned.m8n8.x4.shared.b16 {%0,%1,%2,%3}, [%4];" \
                 : "=r"(r0), "=r"(r1), "=r"(r2), "=r"(r3) : "r"(addr))

__device__ __forceinline__ void mma16816(float* d, const uint32_t* a,
                                         uint32_t b0, uint32_t b1) {
    asm volatile(
        "mma.sync.aligned.m16n8k16.row.col.f32.bf16.bf16.f32 "
        "{%0,%1,%2,%3}, {%4,%5,%6,%7}, {%8,%9}, {%0,%1,%2,%3};"
        : "+f"(d[0]), "+f"(d[1]), "+f"(d[2]), "+f"(d[3])
        : "r"(a[0]), "r"(a[1]), "r"(a[2]), "r"(a[3]), "r"(b0), "r"(b1));
}

__device__ __forceinline__ uint32_t sw128(uint32_t off) {
    return off ^ ((off >> 3) & 0x70);
}
__device__ __forceinline__ uint32_t pack_bf16(float x, float y) {
    __nv_bfloat162 t;
    t.x = __float2bfloat16(x);
    t.y = __float2bfloat16(y);
    return *reinterpret_cast<uint32_t*>(&t);
}

// ======================= bf16x3 tensor-core GEMM ==============================
// CTA tile 128(M) x 256(N), BK=64, 8 warps (2m x 4n), warp tile 64x64.
// Stage: Ah(16K) Al(16K) Bh(32K) Bl(32K) = 96 KB; 2 stages = 192 KB.
#define SA_H 0
#define SA_L 16384
#define SB_H 32768
#define SB_L 65536
#define STAGE_B 98304
#define GSMEM_TOTAL (2 * STAGE_B)   // 192 KB

template <bool RELU, bool RES, bool SPLIT>
__global__ void __launch_bounds__(256, 1) mma_gemm(
    const __nv_bfloat16* __restrict__ Ah, const __nv_bfloat16* __restrict__ Al,
    const __nv_bfloat16* __restrict__ Bh, const __nv_bfloat16* __restrict__ Bl,
    const float* __restrict__ bias, const float* __restrict__ R,
    float* __restrict__ C, __nv_bfloat16* __restrict__ Chi,
    __nv_bfloat16* __restrict__ Clo, int M, int N, int K) {
    extern __shared__ char smem[];
    const uint32_t sb = smem_u32(smem);
    const int tid = threadIdx.x;
    const int lane = tid & 31;
    const int w = tid >> 5;
    const int wm = w >> 2;        // 0..1 (64 rows)
    const int wn = w & 3;         // 0..3 (64 cols)
    const int bm = blockIdx.y * 128;
    const int bn = blockIdx.x * 256;

    const int n_iter = K >> 6;
    const int frow = tid >> 3;    // 0..31
    const int fch = tid & 7;

    auto issue = [&](int it) {
        const int buf = it & 1;
        const int kt = it << 6;
        const uint32_t base = sb + buf * STAGE_B;
        #pragma unroll
        for (int t = 0; t < 4; ++t) {
            const int row = frow + t * 32;
            const uint32_t so = sw128((uint32_t)(row * 128 + fch * 16));
            const size_t ga = (size_t)(bm + row) * K + kt + fch * 8;
            CP_ASYNC16(base + SA_H + so, Ah + ga);
            CP_ASYNC16(base + SA_L + so, Al + ga);
        }
        #pragma unroll
        for (int t = 0; t < 8; ++t) {
            const int row = frow + t * 32;
            const uint32_t so = sw128((uint32_t)(row * 128 + fch * 16));
            const size_t gb = (size_t)(bn + row) * K + kt + fch * 8;
            CP_ASYNC16(base + SB_H + so, Bh + gb);
            CP_ASYNC16(base + SB_L + so, Bl + gb);
        }
        CP_COMMIT();
    };

    float acc[4][8][4];
    #pragma unroll
    for (int mt = 0; mt < 4; ++mt)
        #pragma unroll
        for (int nt = 0; nt < 8; ++nt)
            #pragma unroll
            for (int e = 0; e < 4; ++e) acc[mt][nt][e] = 0.f;

    issue(0);
    if (n_iter > 1) issue(1);

    const int a_row_base = wm * 64 + (lane & 15);
    const int a_cb = (lane >> 4) << 4;
    const int b_row_base = wn * 64 + (lane & 7) + ((lane >> 4) << 3);
    const int b_cb = ((lane >> 3) & 1) << 4;

    for (int it = 0; it < n_iter; ++it) {
        const int buf = it & 1;
        if (it + 1 < n_iter) { CP_WAIT1(); } else { CP_WAIT0(); }
        __syncthreads();

        const uint32_t tAh = sb + buf * STAGE_B + SA_H;
        const uint32_t tAl = sb + buf * STAGE_B + SA_L;
        const uint32_t tBh = sb + buf * STAGE_B + SB_H;
        const uint32_t tBl = sb + buf * STAGE_B + SB_L;

        #pragma unroll
        for (int ks = 0; ks < 4; ++ks) {
            uint32_t ah[4][4], al[4][4];
            #pragma unroll
            for (int mt = 0; mt < 4; ++mt) {
                const uint32_t off = sw128((uint32_t)((a_row_base + mt * 16) * 128 + ks * 32 + a_cb));
                LDSM4(ah[mt][0], ah[mt][1], ah[mt][2], ah[mt][3], tAh + off);
                LDSM4(al[mt][0], al[mt][1], al[mt][2], al[mt][3], tAl + off);
            }
            #pragma unroll
            for (int g = 0; g < 4; ++g) {
                uint32_t bh[4], bl[4];
                const uint32_t off = sw128((uint32_t)((b_row_base + g * 16) * 128 + ks * 32 + b_cb));
                LDSM4(bh[0], bh[1], bh[2], bh[3], tBh + off);
                LDSM4(bl[0], bl[1], bl[2], bl[3], tBl + off);
                #pragma unroll
                for (int mt = 0; mt < 4; ++mt) {
                    mma16816(acc[mt][2 * g],     ah[mt], bh[0], bh[1]);
                    mma16816(acc[mt][2 * g],     al[mt], bh[0], bh[1]);
                    mma16816(acc[mt][2 * g],     ah[mt], bl[0], bl[1]);
                    mma16816(acc[mt][2 * g + 1], ah[mt], bh[2], bh[3]);
                    mma16816(acc[mt][2 * g + 1], al[mt], bh[2], bh[3]);
                    mma16816(acc[mt][2 * g + 1], ah[mt], bl[2], bl[3]);
                }
            }
        }
        __syncthreads();
        if (it + 2 < n_iter) issue(it + 2);
    }

    const int r0 = lane >> 2;
    const int c0 = (lane & 3) * 2;
    #pragma unroll
    for (int mt = 0; mt < 4; ++mt) {
        #pragma unroll
        for (int rr = 0; rr < 2; ++rr) {
            const size_t m = (size_t)(bm + wm * 64 + mt * 16 + r0 + rr * 8);
            #pragma unroll
            for (int nt = 0; nt < 8; ++nt) {
                const int n = bn + wn * 64 + nt * 8 + c0;
                float2 bv = *(const float2*)(bias + n);
                float vx = acc[mt][nt][rr * 2 + 0] + bv.x;
                float vy = acc[mt][nt][rr * 2 + 1] + bv.y;
                if (RES) {
                    float2 rv = *(const float2*)(R + m * N + n);
                    vx += rv.x; vy += rv.y;
                }
                if (RELU) { vx = fmaxf(vx, 0.f); vy = fmaxf(vy, 0.f); }
                if (SPLIT) {
                    __nv_bfloat16 hx = __float2bfloat16(vx);
                    __nv_bfloat16 hy = __float2bfloat16(vy);
                    __nv_bfloat16 lx = __float2bfloat16(vx - __bfloat162float(hx));
                    __nv_bfloat16 ly = __float2bfloat16(vy - __bfloat162float(hy));
                    *(__nv_bfloat162*)(Chi + m * N + n) = __nv_bfloat162(hx, hy);
                    *(__nv_bfloat162*)(Clo + m * N + n) = __nv_bfloat162(lx, ly);
                } else {
                    *(float2*)(C + m * N + n) = make_float2(vx, vy);
                }
            }
        }
    }
}

// ---------------- weight transpose + split (bf162 packed stores) -------------
// W[K,N] fp32 -> WT[N,K] bf16 hi/lo. Tile 32(k) x 32(n), block (16,16).
__global__ void wsplit_kernel(const float* __restrict__ W, __nv_bfloat16* __restrict__ Th,
                              __nv_bfloat16* __restrict__ Tl, int K, int N) {
    __shared__ float t[32][33];
    const int n0 = blockIdx.x * 32, k0 = blockIdx.y * 32;
    const int tx = threadIdx.x, ty = threadIdx.y;   // 16 x 16
    #pragma unroll
    for (int di = 0; di < 2; ++di)
        #pragma unroll
        for (int dj = 0; dj < 2; ++dj)
            t[ty + di * 16][tx + dj * 16] = W[(size_t)(k0 + ty + di * 16) * N + n0 + tx + dj * 16];
    __syncthreads();
    #pragma unroll
    for (int dn = 0; dn < 2; ++dn) {
        const int n = ty + dn * 16;
        const float v0 = t[2 * tx][n];
        const float v1 = t[2 * tx + 1][n];
        __nv_bfloat16 h0 = __float2bfloat16(v0), h1 = __float2bfloat16(v1);
        __nv_bfloat16 l0 = __float2bfloat16(v0 - __bfloat162float(h0));
        __nv_bfloat16 l1 = __float2bfloat16(v1 - __bfloat162float(h1));
        const size_t o = (size_t)(n0 + n) * K + k0 + 2 * tx;
        *(__nv_bfloat162*)(Th + o) = __nv_bfloat162(h0, h1);
        *(__nv_bfloat162*)(Tl + o) = __nv_bfloat162(l0, l1);
    }
}

__global__ void concat3_kernel(const float* __restrict__ a, const float* __restrict__ b,
                               const float* __restrict__ c, float* __restrict__ o) {
    int i = blockIdx.x * 256 + threadIdx.x;
    if (i < 1024) o[i] = a[i];
    else if (i < 2048) o[i] = b[i - 1024];
    else if (i < 3072) o[i] = c[i - 2048];
}

// ---------------- LayerNorm -> bf16 hi/lo split ----------------
__global__ void ln_split_kernel(const float* __restrict__ x, const float* __restrict__ gam,
                                const float* __restrict__ bet,
                                __nv_bfloat16* __restrict__ hi, __nv_bfloat16* __restrict__ lo) {
    int row = blockIdx.x;
    const float* xr = x + (size_t)row * D_MODEL;
    int tid = threadIdx.x;
    float4 v = *(const float4*)(xr + tid * 4);
    float s  = v.x + v.y + v.z + v.w;
    float ss = v.x * v.x + v.y * v.y + v.z * v.z + v.w * v.w;
    #pragma unroll
    for (int o = 16; o > 0; o >>= 1) {
        s  += __shfl_xor_sync(0xffffffffu, s, o);
        ss += __shfl_xor_sync(0xffffffffu, ss, o);
    }
    __shared__ float sh[16];
    int wid = tid >> 5, lane = tid & 31;
    if (lane == 0) { sh[wid] = s; sh[8 + wid] = ss; }
    __syncthreads();
    if (tid == 0) {
        float a = 0.f, b = 0.f;
        #pragma unroll
        for (int w = 0; w < 8; ++w) { a += sh[w]; b += sh[8 + w]; }
        sh[0] = a; sh[8] = b;
    }
    __syncthreads();
    float mu  = sh[0] * (1.0f / D_MODEL);
    float var = sh[8] * (1.0f / D_MODEL) - mu * mu;
    float r = rsqrtf(var + 1e-5f);
    float4 gv = *(const float4*)(gam + tid * 4);
    float4 bv = *(const float4*)(bet + tid * 4);
    float o4[4];
    o4[0] = (v.x - mu) * r * gv.x + bv.x;
    o4[1] = (v.y - mu) * r * gv.y + bv.y;
    o4[2] = (v.z - mu) * r * gv.z + bv.z;
    o4[3] = (v.w - mu) * r * gv.w + bv.w;
    __nv_bfloat16 h4[4], l4[4];
    #pragma unroll
    for (int j = 0; j < 4; ++j) {
        h4[j] = __float2bfloat16(o4[j]);
        l4[j] = __float2bfloat16(o4[j] - __bfloat162float(h4[j]));
    }
    size_t base = (size_t)row * D_MODEL + tid * 4;
    __nv_bfloat162* ph = (__nv_bfloat162*)(hi + base);
    __nv_bfloat162* pl = (__nv_bfloat162*)(lo + base);
    ph[0] = __nv_bfloat162(h4[0], h4[1]); ph[1] = __nv_bfloat162(h4[2], h4[3]);
    pl[0] = __nv_bfloat162(l4[0], l4[1]); pl[1] = __nv_bfloat162(l4[2], l4[3]);
}

// =============== tensor-core flash attention (bf16x3 QK, bf16 PV) =============
#define SQH 0
#define SQL 16384
#define SKH(b) (32768 + (b) * 24576)
#define SKL(b) (32768 + (b) * 24576 + 8192)
#define SVS(b) (32768 + (b) * 24576 + 16384)
#define SVT 81920
#define SMSK(b) (90112 + (b) * 256)
#define ASMEM 90624
#define NKV (SEQ / 64)   // 32

__global__ void __launch_bounds__(256, 1) attn_tc_kernel(
    const __nv_bfloat16* __restrict__ QKVh, const __nv_bfloat16* __restrict__ QKVl,
    const int* __restrict__ mask,
    __nv_bfloat16* __restrict__ Ohi, __nv_bfloat16* __restrict__ Olo) {
    extern __shared__ char smem[];
    const uint32_t sb = smem_u32(smem);
    const int tid = threadIdx.x;
    const int lane = tid & 31;
    const int w = tid >> 5;
    const int q0 = blockIdx.x * 128;
    const int b = blockIdx.y >> 4;
    const int h = blockIdx.y & 15;
    const size_t tok0 = (size_t)b * SEQ;

    const __nv_bfloat16* Qh_g = QKVh + (tok0 + q0) * QKV_N + h * 64;
    const __nv_bfloat16* Ql_g = QKVl + (tok0 + q0) * QKV_N + h * 64;
    const __nv_bfloat16* Kh_g = QKVh + tok0 * QKV_N + 1024 + h * 64;
    const __nv_bfloat16* Kl_g = QKVl + tok0 * QKV_N + 1024 + h * 64;
    const __nv_bfloat16* Vh_g = QKVh + tok0 * QKV_N + 2048 + h * 64;
    const int* mask_b = mask + b * SEQ;

    auto issue_tile = [&](int t) {
        const int buf = t & 1;
        const int row = tid >> 2;
        const int ch0 = (tid & 3) * 2;
        const size_t roff = (size_t)(t * 64 + row) * QKV_N;
        #pragma unroll
        for (int c = 0; c < 2; ++c) {
            const int ch = ch0 + c;
            const uint32_t so = sw128((uint32_t)(row * 128 + ch * 16));
            CP_ASYNC16(sb + SKH(buf) + so, Kh_g + roff + ch * 8);
            CP_ASYNC16(sb + SKL(buf) + so, Kl_g + roff + ch * 8);
            CP_ASYNC16(sb + SVS(buf) + so, Vh_g + roff + ch * 8);
        }
        if (tid < 16) CP_ASYNC16(sb + SMSK(buf) + tid * 16, mask_b + t * 64 + tid * 4);
        CP_COMMIT();
    };

    {
        const int row = tid >> 1;
        const int chb = (tid & 1) * 4;
        #pragma unroll
        for (int c = 0; c < 4; ++c) {
            const int ch = chb + c;
            const uint32_t so = sw128((uint32_t)(row * 128 + ch * 16));
            CP_ASYNC16(sb + SQH + so, Qh_g + (size_t)row * QKV_N + ch * 8);
            CP_ASYNC16(sb + SQL + so, Ql_g + (size_t)row * QKV_N + ch * 8);
        }
    }
    issue_tile(0);
    issue_tile(1);

    const int a_row = 16 * w + (lane & 15);
    const int a_cb = (lane >> 4) << 4;
    const int b_row = (lane & 7) + ((lane >> 4) << 3);
    const int b_cb = ((lane >> 3) & 1) << 4;

    float m0 = -1e30f, m1 = -1e30f, l0 = 0.f, l1 = 0.f;
    float ctx[8][4];
    #pragma unroll
    for (int dt = 0; dt < 8; ++dt)
        #pragma unroll
        for (int e = 0; e < 4; ++e) ctx[dt][e] = 0.f;

    for (int t = 0; t < NKV; ++t) {
        const int buf = t & 1;
        if (t == NKV - 1) { CP_WAIT0(); } else { CP_WAIT1(); }
        __syncthreads();

        float s[8][4];
        #pragma unroll
        for (int nt = 0; nt < 8; ++nt)
            #pragma unroll
            for (int e = 0; e < 4; ++e) s[nt][e] = 0.f;

        #pragma unroll
        for (int ks = 0; ks < 4; ++ks) {
            uint32_t ah[4], al[4];
            {
                const uint32_t off = sw128((uint32_t)(a_row * 128 + ks * 32 + a_cb));
                LDSM4(ah[0], ah[1], ah[2], ah[3], sb + SQH + off);
                LDSM4(al[0], al[1], al[2], al[3], sb + SQL + off);
            }
            #pragma unroll
            for (int g = 0; g < 4; ++g) {
                uint32_t bh[4], bl[4];
                const uint32_t off = sw128((uint32_t)((g * 16 + b_row) * 128 + ks * 32 + b_cb));
                LDSM4(bh[0], bh[1], bh[2], bh[3], sb + SKH(buf) + off);
                LDSM4(bl[0], bl[1], bl[2], bl[3], sb + SKL(buf) + off);
                mma16816(s[2 * g],     ah, bh[0], bh[1]);
                mma16816(s[2 * g],     al, bh[0], bh[1]);
                mma16816(s[2 * g],     ah, bl[0], bl[1]);
                mma16816(s[2 * g + 1], ah, bh[2], bh[3]);
                mma16816(s[2 * g + 1], al, bh[2], bh[3]);
                mma16816(s[2 * g + 1], ah, bl[2], bl[3]);
            }
        }

        const int cbase = (lane & 3) * 2;
        float mx0 = -1e30f, mx1 = -1e30f;
        #pragma unroll
        for (int nt = 0; nt < 8; ++nt) {
            const int n0 = nt * 8 + cbase;
            const int mi0 = *(const int*)(smem + SMSK(buf) + n0 * 4);
            const int mi1 = *(const int*)(smem + SMSK(buf) + (n0 + 1) * 4);
            const float ad0 = (mi0 == 0) ? -1e30f : 0.f;
            const float ad1 = (mi1 == 0) ? -1e30f : 0.f;
            s[nt][0] = s[nt][0] * 0.125f + ad0;
            s[nt][1] = s[nt][1] * 0.125f + ad1;
            s[nt][2] = s[nt][2] * 0.125f + ad0;
            s[nt][3] = s[nt][3] * 0.125f + ad1;
            mx0 = fmaxf(mx0, fmaxf(s[nt][0], s[nt][1]));
            mx1 = fmaxf(mx1, fmaxf(s[nt][2], s[nt][3]));
        }
        mx0 = fmaxf(mx0, __shfl_xor_sync(0xffffffffu, mx0, 1));
        mx0 = fmaxf(mx0, __shfl_xor_sync(0xffffffffu, mx0, 2));
        mx1 = fmaxf(mx1, __shfl_xor_sync(0xffffffffu, mx1, 1));
        mx1 = fmaxf(mx1, __shfl_xor_sync(0xffffffffu, mx1, 2));
        const float mn0 = fmaxf(m0, mx0), mn1 = fmaxf(m1, mx1);
        const float al0 = __expf(m0 - mn0), al1 = __expf(m1 - mn1);
        float ls0 = 0.f, ls1 = 0.f;
        #pragma unroll
        for (int nt = 0; nt < 8; ++nt) {
            s[nt][0] = __expf(s[nt][0] - mn0); ls0 += s[nt][0];
            s[nt][1] = __expf(s[nt][1] - mn0); ls0 += s[nt][1];
            s[nt][2] = __expf(s[nt][2] - mn1); ls1 += s[nt][2];
            s[nt][3] = __expf(s[nt][3] - mn1); ls1 += s[nt][3];
        }
        ls0 += __shfl_xor_sync(0xffffffffu, ls0, 1);
        ls0 += __shfl_xor_sync(0xffffffffu, ls0, 2);
        ls1 += __shfl_xor_sync(0xffffffffu, ls1, 1);
        ls1 += __shfl_xor_sync(0xffffffffu, ls1, 2);
        l0 = l0 * al0 + ls0; l1 = l1 * al1 + ls1;
        m0 = mn0; m1 = mn1;
        #pragma unroll
        for (int dt = 0; dt < 8; ++dt) {
            ctx[dt][0] *= al0; ctx[dt][1] *= al0;
            ctx[dt][2] *= al1; ctx[dt][3] *= al1;
        }
        uint32_t pA[4][4];
        #pragma unroll
        for (int j = 0; j < 4; ++j) {
            pA[j][0] = pack_bf16(s[2 * j][0],     s[2 * j][1]);
            pA[j][1] = pack_bf16(s[2 * j][2],     s[2 * j][3]);
            pA[j][2] = pack_bf16(s[2 * j + 1][0], s[2 * j + 1][1]);
            pA[j][3] = pack_bf16(s[2 * j + 1][2], s[2 * j + 1][3]);
        }

        #pragma unroll
        for (int i = 0; i < 8; ++i) {
            const int linear = tid + i * 256;
            const int key = linear & 63;
            const int dp = linear >> 6;
            const uint32_t v = *(const uint32_t*)(smem + SVS(buf) + sw128((uint32_t)(key * 128 + dp * 4)));
            *(uint16_t*)(smem + SVT + sw128((uint32_t)((2 * dp) * 128 + key * 2)))     = (uint16_t)(v & 0xffff);
            *(uint16_t*)(smem + SVT + sw128((uint32_t)((2 * dp + 1) * 128 + key * 2))) = (uint16_t)(v >> 16);
        }
        __syncthreads();

        if (t + 2 < NKV) issue_tile(t + 2);

        #pragma unroll
        for (int j = 0; j < 4; ++j) {
            #pragma unroll
            for (int g = 0; g < 4; ++g) {
                uint32_t bv[4];
                const uint32_t off = sw128((uint32_t)((g * 16 + b_row) * 128 + j * 32 + b_cb));
                LDSM4(bv[0], bv[1], bv[2], bv[3], sb + SVT + off);
                mma16816(ctx[2 * g],     pA[j], bv[0], bv[1]);
                mma16816(ctx[2 * g + 1], pA[j], bv[2], bv[3]);
            }
        }
    }

    const float inv0 = 1.0f / l0, inv1 = 1.0f / l1;
    const int row0 = q0 + 16 * w + (lane >> 2);
    #pragma unroll
    for (int dt = 0; dt < 8; ++dt) {
        const int d = h * 64 + dt * 8 + (lane & 3) * 2;
        float o0 = ctx[dt][0] * inv0, o1 = ctx[dt][1] * inv0;
        float o2 = ctx[dt][2] * inv1, o3 = ctx[dt][3] * inv1;
        __nv_bfloat16 h0 = __float2bfloat16(o0), h1b = __float2bfloat16(o1);
        __nv_bfloat16 h2 = __float2bfloat16(o2), h3 = __float2bfloat16(o3);
        size_t i0 = (tok0 + row0) * D_MODEL + d;
        size_t i1 = (tok0 + row0 + 8) * D_MODEL + d;
        *(__nv_bfloat162*)(Ohi + i0) = __nv_bfloat162(h0, h1b);
        *(__nv_bfloat162*)(Ohi + i1) = __nv_bfloat162(h2, h3);
        *(__nv_bfloat162*)(Olo + i0) = __nv_bfloat162(
            __float2bfloat16(o0 - __bfloat162float(h0)), __float2bfloat16(o1 - __bfloat162float(h1b)));
        *(__nv_bfloat162*)(Olo + i1) = __nv_bfloat162(
            __float2bfloat16(o2 - __bfloat162float(h2)), __float2bfloat16(o3 - __bfloat162float(h3)));
    }
}

// ---------------- launch ----------------
extern "C" void kernel_launch(void* const* d_in, const int* in_sizes, int n_in,
                              void* d_out, int out_size) {
    const float* x     = (const float*)d_in[0];
    const int*   mask  = (const int*)d_in[1];
    const float* wq    = (const float*)d_in[2];
    const float* bq    = (const float*)d_in[3];
    const float* wk    = (const float*)d_in[4];
    const float* bk    = (const float*)d_in[5];
    const float* wv    = (const float*)d_in[6];
    const float* bv    = (const float*)d_in[7];
    const float* wo    = (const float*)d_in[8];
    const float* bo    = (const float*)d_in[9];
    const float* ln1_g = (const float*)d_in[10];
    const float* ln1_b = (const float*)d_in[11];
    const float* ln2_g = (const float*)d_in[12];
    const float* ln2_b = (const float*)d_in[13];
    const float* w1    = (const float*)d_in[14];
    const float* b1    = (const float*)d_in[15];
    const float* w2    = (const float*)d_in[16];
    const float* b2    = (const float*)d_in[17];
    float* out = (float*)d_out;

    float *x1, *bqkv;
    __nv_bfloat16 *ah, *al, *fh, *fl, *wh, *wl;
    cudaGetSymbolAddress((void**)&x1,   g_x1);
    cudaGetSymbolAddress((void**)&bqkv, g_bqkv);
    cudaGetSymbolAddress((void**)&ah,   s_ah);
    cudaGetSymbolAddress((void**)&al,   s_al);
    cudaGetSymbolAddress((void**)&fh,   s_fh);
    cudaGetSymbolAddress((void**)&fl,   s_fl);
    cudaGetSymbolAddress((void**)&wh,   s_wh);
    cudaGetSymbolAddress((void**)&wl,   s_wl);

    cudaFuncSetAttribute(mma_gemm<false, false, true>, cudaFuncAttributeMaxDynamicSharedMemorySize, GSMEM_TOTAL);
    cudaFuncSetAttribute(mma_gemm<false, true, false>, cudaFuncAttributeMaxDynamicSharedMemorySize, GSMEM_TOTAL);
    cudaFuncSetAttribute(mma_gemm<true, false, true>,  cudaFuncAttributeMaxDynamicSharedMemorySize, GSMEM_TOTAL);
    cudaFuncSetAttribute(attn_tc_kernel, cudaFuncAttributeMaxDynamicSharedMemorySize, ASMEM);

    dim3 wsb(16, 16);

    // --- residual 1 ---
    ln_split_kernel<<<NTOK, 256>>>(x, ln1_g, ln1_b, ah, al);
    wsplit_kernel<<<dim3(32, 32), wsb>>>(wq, wh, wl, D_MODEL, D_MODEL);
    wsplit_kernel<<<dim3(32, 32), wsb>>>(wk, wh + 1024 * 1024, wl + 1024 * 1024, D_MODEL, D_MODEL);
    wsplit_kernel<<<dim3(32, 32), wsb>>>(wv, wh + 2 * 1024 * 1024, wl + 2 * 1024 * 1024, D_MODEL, D_MODEL);
    concat3_kernel<<<12, 256>>>(bq, bk, bv, bqkv);

    mma_gemm<false, false, true><<<dim3(QKV_N / 256, NTOK / 128), 256, GSMEM_TOTAL>>>(
        ah, al, wh, wl, bqkv, nullptr, nullptr, fh, fl, NTOK, QKV_N, D_MODEL);

    attn_tc_kernel<<<dim3(SEQ / 128, BATCH * N_HEADS), 256, ASMEM>>>(fh, fl, mask, ah, al);

    wsplit_kernel<<<dim3(32, 32), wsb>>>(wo, wh, wl, D_MODEL, D_MODEL);
    mma_gemm<false, true, false><<<dim3(D_MODEL / 256, NTOK / 128), 256, GSMEM_TOTAL>>>(
        ah, al, wh, wl, bo, x, x1, nullptr, nullptr, NTOK, D_MODEL, D_MODEL);

    // --- residual 2 ---
    ln_split_kernel<<<NTOK, 256>>>(x1, ln2_g, ln2_b, ah, al);
    wsplit_kernel<<<dim3(FF_DIM / 32, D_MODEL / 32), wsb>>>(w1, wh, wl, D_MODEL, FF_DIM);
    mma_gemm<true, false, true><<<dim3(FF_DIM / 256, NTOK / 128), 256, GSMEM_TOTAL>>>(
        ah, al, wh, wl, b1, nullptr, nullptr, fh, fl, NTOK, FF_DIM, D_MODEL);

    wsplit_kernel<<<dim3(D_MODEL / 32, FF_DIM / 32), wsb>>>(w2, wh, wl, FF_DIM, D_MODEL);
    mma_gemm<false, true, false><<<dim3(D_MODEL / 256, NTOK / 128), 256, GSMEM_TOTAL>>>(
        fh, fl, wh, wl, b2, x1, out, nullptr, nullptr, NTOK, D_MODEL, FF_DIM);
}